// round 1
// baseline (speedup 1.0000x reference)
#include <cuda_runtime.h>
#include <math.h>

#define D_   768
#define H_   12
#define L_   6
#define B_   4
#define N_   1024
#define DH_  64
#define ROWS (B_*N_)      /* 4096 */
#define D3   (3*D_)       /* 2304 */
#define DFF  (4*D_)       /* 3072 */
#define ZHB  (B_*H_)      /* 48   */

// ---------------- scratch (static device globals; no runtime alloc) ----------
__device__ float g_x   [ROWS*(size_t)D_];
__device__ float g_xn  [ROWS*(size_t)D_];
__device__ float g_qkv [ROWS*(size_t)D3];
__device__ float g_sc  [(size_t)ZHB*N_*N_];   // 201 MB attention scores
__device__ float g_attn[ROWS*(size_t)D_];
__device__ float g_h   [ROWS*(size_t)DFF];

// ---------------- LayerNorm: one block per row (D=768, 256 thr, 3 elem/thr) --
__global__ void ln_kernel(const float* __restrict__ x,
                          const float* __restrict__ g,
                          const float* __restrict__ b,
                          float* __restrict__ y) {
    const int row = blockIdx.x;
    const float* xr = x + (size_t)row * D_;
    float*       yr = y + (size_t)row * D_;
    const int tid = threadIdx.x;

    float v[3], s = 0.f, s2 = 0.f;
#pragma unroll
    for (int i = 0; i < 3; ++i) {
        float t = xr[tid + i * 256];
        v[i] = t; s += t; s2 += t * t;
    }
#pragma unroll
    for (int o = 16; o; o >>= 1) {
        s  += __shfl_xor_sync(0xffffffffu, s,  o);
        s2 += __shfl_xor_sync(0xffffffffu, s2, o);
    }
    __shared__ float shs[8], shs2[8];
    const int w = tid >> 5;
    if ((tid & 31) == 0) { shs[w] = s; shs2[w] = s2; }
    __syncthreads();
    s = 0.f; s2 = 0.f;
#pragma unroll
    for (int i = 0; i < 8; ++i) { s += shs[i]; s2 += shs2[i]; }
    const float mean = s * (1.f / D_);
    const float var  = s2 * (1.f / D_) - mean * mean;   // biased, matches jnp.var
    const float rstd = rsqrtf(var + 1e-5f);
#pragma unroll
    for (int i = 0; i < 3; ++i) {
        int c = tid + i * 256;
        yr[c] = (v[i] - mean) * rstd * g[c] + b[c];
    }
}

// ---------------- row softmax over 1024 (one block per row) ------------------
__global__ void softmax_k(float* __restrict__ sc) {
    const size_t row = blockIdx.x;
    float* p = sc + row * (size_t)N_;
    const int tid = threadIdx.x;

    float v[4], mx = -3.4e38f;
#pragma unroll
    for (int i = 0; i < 4; ++i) { v[i] = p[tid + i * 256]; mx = fmaxf(mx, v[i]); }
#pragma unroll
    for (int o = 16; o; o >>= 1) mx = fmaxf(mx, __shfl_xor_sync(0xffffffffu, mx, o));
    __shared__ float sh[8];
    const int w = tid >> 5;
    if ((tid & 31) == 0) sh[w] = mx;
    __syncthreads();
#pragma unroll
    for (int i = 0; i < 8; ++i) mx = fmaxf(mx, sh[i]);
    __syncthreads();

    float s = 0.f;
#pragma unroll
    for (int i = 0; i < 4; ++i) { v[i] = __expf(v[i] - mx); s += v[i]; }
#pragma unroll
    for (int o = 16; o; o >>= 1) s += __shfl_xor_sync(0xffffffffu, s, o);
    if ((tid & 31) == 0) sh[w] = s;
    __syncthreads();
    s = 0.f;
#pragma unroll
    for (int i = 0; i < 8; ++i) s += sh[i];
    const float r = 1.f / s;
#pragma unroll
    for (int i = 0; i < 4; ++i) p[tid + i * 256] = v[i] * r;
}

// ---------------- generic tiled SIMT GEMM with fused epilogues ---------------
// FLAGS: 1=bias  2=gelu(exact)  4=residual-add  8=alpha*acc+spatial-bias  16=transB
// Batched via z = blockIdx.z decomposed as (zo, zi) = (z/zdiv, z%zdiv)
// with independent outer/inner pointer strides per operand.
template<int BM, int BN, int BK, int TM, int TN, int FLAGS>
__global__ void __launch_bounds__((BM/TM)*(BN/TN))
gemm_k(const float* __restrict__ A, const float* __restrict__ B,
       float* __restrict__ C,
       int K, int lda, int ldb, int ldc,
       long aOut, long aIn, long bOut, long bIn, long cOut, long cIn, int zdiv,
       const float* __restrict__ bias,
       const float* __restrict__ resid, int ldres,
       const float* __restrict__ swb, long swOut, int ldsw,
       float alpha) {
    constexpr int THREADS = (BM/TM)*(BN/TN);
    constexpr int RX = BN / TN;   // column groups
    constexpr int RY = BM / TM;   // row groups
    __shared__ float As[BK][BM + 1];
    __shared__ float Bs[BK][BN + 1];

    const int tid = threadIdx.x;
    const int bn = blockIdx.x * BN;
    const int bm = blockIdx.y * BM;
    const int z  = blockIdx.z;
    const int zo = z / zdiv, zi = z - zo * zdiv;
    A += zo * aOut + zi * aIn;
    B += zo * bOut + zi * bIn;
    C += zo * cOut + zi * cIn;

    const int tx = tid % RX;
    const int ty = tid / RX;
    float acc[TM][TN] = {};

    for (int k0 = 0; k0 < K; k0 += BK) {
        // A tile: As[k][m] = A[bm+m][k0+k]
#pragma unroll
        for (int t = tid; t < BM * BK; t += THREADS) {
            int i = t / BK, j = t % BK;
            As[j][i] = A[(long)(bm + i) * lda + (k0 + j)];
        }
        if (FLAGS & 16) {  // transposed B: Bs[k][n] = B[bn+n][k0+k]
#pragma unroll
            for (int t = tid; t < BN * BK; t += THREADS) {
                int j = t / BK, i = t % BK;
                Bs[i][j] = B[(long)(bn + j) * ldb + (k0 + i)];
            }
        } else {           // Bs[k][n] = B[k0+k][bn+n]
#pragma unroll
            for (int t = tid; t < BK * BN; t += THREADS) {
                int i = t / BN, j = t % BN;
                Bs[i][j] = B[(long)(k0 + i) * ldb + (bn + j)];
            }
        }
        __syncthreads();
#pragma unroll
        for (int kk = 0; kk < BK; ++kk) {
            float ra[TM], rb[TN];
#pragma unroll
            for (int m = 0; m < TM; ++m) ra[m] = As[kk][ty + m * RY];
#pragma unroll
            for (int n = 0; n < TN; ++n) rb[n] = Bs[kk][tx + n * RX];
#pragma unroll
            for (int m = 0; m < TM; ++m)
#pragma unroll
                for (int n = 0; n < TN; ++n)
                    acc[m][n] += ra[m] * rb[n];
        }
        __syncthreads();
    }

    const float* swp = (FLAGS & 8) ? (swb + (long)zo * swOut) : nullptr;
#pragma unroll
    for (int m = 0; m < TM; ++m) {
        const int row = bm + ty + m * RY;
#pragma unroll
        for (int n = 0; n < TN; ++n) {
            const int col = bn + tx + n * RX;
            float v = acc[m][n];
            if (FLAGS & 8)  v = v * alpha + swp[(long)row * ldsw + col];
            if (FLAGS & 1)  v += bias[col];
            if (FLAGS & 2)  v = 0.5f * v * (1.f + erff(v * 0.70710678118654752f));
            if (FLAGS & 4)  v += resid[(long)row * ldres + col];
            C[(long)row * ldc + col] = v;
        }
    }
}

// ---------------- launch ------------------------------------------------------
extern "C" void kernel_launch(void* const* d_in, const int* in_sizes, int n_in,
                              void* d_out, int out_size) {
    const float* x_in  = (const float*)d_in[0];
    const float* sw    = (const float*)d_in[1];
    const float* ln1g  = (const float*)d_in[2];
    const float* ln1b  = (const float*)d_in[3];
    const float* wqkv  = (const float*)d_in[4];
    const float* wout  = (const float*)d_in[5];
    const float* bout  = (const float*)d_in[6];
    const float* ln2g  = (const float*)d_in[7];
    const float* ln2b  = (const float*)d_in[8];
    const float* w1    = (const float*)d_in[9];
    const float* b1    = (const float*)d_in[10];
    const float* w2    = (const float*)d_in[11];
    const float* b2    = (const float*)d_in[12];
    float* out = (float*)d_out;

    float *px, *pxn, *pqkv, *psc, *pattn, *ph;
    cudaGetSymbolAddress((void**)&px,    g_x);
    cudaGetSymbolAddress((void**)&pxn,   g_xn);
    cudaGetSymbolAddress((void**)&pqkv,  g_qkv);
    cudaGetSymbolAddress((void**)&psc,   g_sc);
    cudaGetSymbolAddress((void**)&pattn, g_attn);
    cudaGetSymbolAddress((void**)&ph,    g_h);

    const long NN  = (long)N_ * N_;
    const long N3D = (long)N_ * D3;

    for (int l = 0; l < L_; ++l) {
        const float* xcur = (l == 0) ? x_in : px;

        // LN1
        ln_kernel<<<ROWS, 256>>>(xcur, ln1g + (long)l * D_, ln1b + (long)l * D_, pxn);

        // QKV: [4096,768] @ [768,2304]
        gemm_k<128,128,16,8,8,0><<<dim3(D3/128, ROWS/128, 1), 256>>>(
            pxn, wqkv + (long)l * D_ * D3, pqkv,
            D_, D_, D3, D3, 0,0,0,0,0,0, 1,
            nullptr, nullptr, 0, nullptr, 0, 0, 0.f);

        // scores = scale * Q K^T + sw  (z = b*H + h, 48 batches, transposed B)
        gemm_k<128,128,16,8,8,8|16><<<dim3(N_/128, N_/128, ZHB), 256>>>(
            pqkv, pqkv + D_, psc,
            DH_, D3, D3, N_,
            N3D, DH_,  N3D, DH_,  (long)H_ * NN, NN,  H_,
            nullptr, nullptr, 0,
            sw, NN, N_, 0.125f);

        // softmax over last dim
        softmax_k<<<ZHB * N_, 256>>>(psc);

        // out = attn @ V  -> g_attn (head-concat layout)
        gemm_k<128,64,16,8,4,0><<<dim3(1, N_/128, ZHB), 256>>>(
            psc, pqkv + 2 * D_, pattn,
            N_, N_, D3, D_,
            (long)H_ * NN, NN,  N3D, DH_,  (long)N_ * D_, DH_,  H_,
            nullptr, nullptr, 0, nullptr, 0, 0, 0.f);

        // proj: g_attn @ w_out + b_out + x  -> g_x
        gemm_k<128,128,16,8,8,1|4><<<dim3(D_/128, ROWS/128, 1), 256>>>(
            pattn, wout + (long)l * D_ * D_, px,
            D_, D_, D_, D_, 0,0,0,0,0,0, 1,
            bout + (long)l * D_, xcur, D_, nullptr, 0, 0, 0.f);

        // LN2
        ln_kernel<<<ROWS, 256>>>(px, ln2g + (long)l * D_, ln2b + (long)l * D_, pxn);

        // FC1 + exact GELU
        gemm_k<128,128,16,8,8,1|2><<<dim3(DFF/128, ROWS/128, 1), 256>>>(
            pxn, w1 + (long)l * D_ * DFF, ph,
            D_, D_, DFF, DFF, 0,0,0,0,0,0, 1,
            b1 + (long)l * DFF, nullptr, 0, nullptr, 0, 0, 0.f);

        // FC2 + bias + residual (last layer writes d_out directly)
        float* cdst = (l == L_ - 1) ? out : px;
        gemm_k<128,128,16,8,8,1|4><<<dim3(D_/128, ROWS/128, 1), 256>>>(
            ph, w2 + (long)l * DFF * D_, cdst,
            DFF, DFF, D_, D_, 0,0,0,0,0,0, 1,
            b2 + (long)l * D_, px, D_, nullptr, 0, 0, 0.f);
    }
}

// round 2
// speedup vs baseline: 2.4874x; 2.4874x over previous
#include <cuda_runtime.h>
#include <math.h>

#define D_   768
#define H_   12
#define L_   6
#define B_   4
#define N_   1024
#define DH_  64
#define ROWS (B_*N_)      /* 4096 */
#define D3   (3*D_)       /* 2304 */
#define DFF  (4*D_)       /* 3072 */
#define ZHB  (B_*H_)      /* 48   */

// ---------------- scratch (static device globals; no runtime alloc) ----------
__device__ float g_x   [ROWS*(size_t)D_];
__device__ float g_xn  [ROWS*(size_t)D_];
__device__ float g_qkv [ROWS*(size_t)D3];
__device__ float g_sc  [(size_t)ZHB*N_*N_];   // 201 MB attention scores
__device__ float g_attn[ROWS*(size_t)D_];
__device__ float g_h   [ROWS*(size_t)DFF];

// ---------------- LayerNorm -------------------------------------------------
__global__ void ln_kernel(const float* __restrict__ x,
                          const float* __restrict__ g,
                          const float* __restrict__ b,
                          float* __restrict__ y) {
    const int row = blockIdx.x;
    const float* xr = x + (size_t)row * D_;
    float*       yr = y + (size_t)row * D_;
    const int tid = threadIdx.x;

    float v[3], s = 0.f, s2 = 0.f;
#pragma unroll
    for (int i = 0; i < 3; ++i) {
        float t = xr[tid + i * 256];
        v[i] = t; s += t; s2 += t * t;
    }
#pragma unroll
    for (int o = 16; o; o >>= 1) {
        s  += __shfl_xor_sync(0xffffffffu, s,  o);
        s2 += __shfl_xor_sync(0xffffffffu, s2, o);
    }
    __shared__ float shs[8], shs2[8];
    const int w = tid >> 5;
    if ((tid & 31) == 0) { shs[w] = s; shs2[w] = s2; }
    __syncthreads();
    s = 0.f; s2 = 0.f;
#pragma unroll
    for (int i = 0; i < 8; ++i) { s += shs[i]; s2 += shs2[i]; }
    const float mean = s * (1.f / D_);
    const float var  = s2 * (1.f / D_) - mean * mean;
    const float rstd = rsqrtf(var + 1e-5f);
#pragma unroll
    for (int i = 0; i < 3; ++i) {
        int c = tid + i * 256;
        yr[c] = (v[i] - mean) * rstd * g[c] + b[c];
    }
}

// ---------------- row softmax over 1024 --------------------------------------
__global__ void softmax_k(float* __restrict__ sc) {
    const size_t row = blockIdx.x;
    float* p = sc + row * (size_t)N_;
    const int tid = threadIdx.x;

    float v[4], mx = -3.4e38f;
#pragma unroll
    for (int i = 0; i < 4; ++i) { v[i] = p[tid + i * 256]; mx = fmaxf(mx, v[i]); }
#pragma unroll
    for (int o = 16; o; o >>= 1) mx = fmaxf(mx, __shfl_xor_sync(0xffffffffu, mx, o));
    __shared__ float sh[8];
    const int w = tid >> 5;
    if ((tid & 31) == 0) sh[w] = mx;
    __syncthreads();
#pragma unroll
    for (int i = 0; i < 8; ++i) mx = fmaxf(mx, sh[i]);
    __syncthreads();

    float s = 0.f;
#pragma unroll
    for (int i = 0; i < 4; ++i) { v[i] = __expf(v[i] - mx); s += v[i]; }
#pragma unroll
    for (int o = 16; o; o >>= 1) s += __shfl_xor_sync(0xffffffffu, s, o);
    if ((tid & 31) == 0) sh[w] = s;
    __syncthreads();
    s = 0.f;
#pragma unroll
    for (int i = 0; i < 8; ++i) s += sh[i];
    const float r = 1.f / s;
#pragma unroll
    for (int i = 0; i < 4; ++i) p[tid + i * 256] = v[i] * r;
}

// ---------------- TF32 tensor-core GEMM --------------------------------------
__device__ __forceinline__ unsigned f2tf(float f) {
    unsigned u;
    asm("cvt.rna.tf32.f32 %0, %1;" : "=r"(u) : "f"(f));
    return u;
}

__device__ __forceinline__ void mma_tf32(float* c,
                                         unsigned a0, unsigned a1, unsigned a2, unsigned a3,
                                         unsigned b0, unsigned b1) {
    asm volatile(
        "mma.sync.aligned.m16n8k8.row.col.f32.tf32.tf32.f32 "
        "{%0,%1,%2,%3}, {%4,%5,%6,%7}, {%8,%9}, {%0,%1,%2,%3};"
        : "+f"(c[0]), "+f"(c[1]), "+f"(c[2]), "+f"(c[3])
        : "r"(a0), "r"(a1), "r"(a2), "r"(a3), "r"(b0), "r"(b1));
}

// FLAGS: 1=bias 2=gelu(exact) 4=residual 8=alpha*acc+spatial-bias 16=transB
// 8 warps as 2(m) x 4(n); warp tile (BM/2) x (BN/4); BK=32.
template<int BM, int BN, int FLAGS>
__global__ void __launch_bounds__(256)
gemm_tf32(const float* __restrict__ A, const float* __restrict__ B,
          float* __restrict__ C,
          int K, int lda, int ldb, int ldc,
          long aOut, long aIn, long bOut, long bIn, long cOut, long cIn, int zdiv,
          const float* __restrict__ bias,
          const float* __restrict__ resid, int ldres,
          const float* __restrict__ swb, long swOut, int ldsw,
          float alpha) {
    constexpr int FM = BM / 32;     // m fragments per warp (16 rows each)
    constexpr int FN = BN / 32;     // n fragments per warp (8 cols each)
    constexpr int BSTR = BN + 8;    // Bs row stride (==8 mod 32)

    __shared__ unsigned As[BM][36];     // m-major, stride 36 (==4 mod 32)
    __shared__ unsigned Bs[32][BSTR];   // k-major

    const int tid  = threadIdx.x;
    const int lane = tid & 31;
    const int gid  = lane >> 2;   // 0..7
    const int tg   = lane & 3;    // 0..3
    const int warp = tid >> 5;
    const int wm   = warp >> 2;   // 0..1
    const int wn   = warp & 3;    // 0..3
    const int mwarp = wm * (BM / 2);
    const int nwarp = wn * (BN / 4);

    const int bn = blockIdx.x * BN;
    const int bm = blockIdx.y * BM;
    const int z  = blockIdx.z;
    const int zo = z / zdiv, zi = z - zo * zdiv;
    A += zo * aOut + zi * aIn;
    B += zo * bOut + zi * bIn;
    C += zo * cOut + zi * cIn;

    float acc[FM][FN][4] = {};

    for (int k0 = 0; k0 < K; k0 += 32) {
        // ---- A tile: As[m][k] (BM x 32), float4 loads along k ----
#pragma unroll
        for (int i = 0; i < (BM * 8) / 256; ++i) {
            int idx = tid + i * 256;
            int r = idx >> 3, c4 = (idx & 7) * 4;
            const float4 v = *(const float4*)&A[(long)(bm + r) * lda + k0 + c4];
            uint4 u = make_uint4(f2tf(v.x), f2tf(v.y), f2tf(v.z), f2tf(v.w));
            *(uint4*)&As[r][c4] = u;
        }
        // ---- B tile: Bs[k][n] (32 x BN) ----
        if (FLAGS & 16) {  // B[n][k] transposed load
#pragma unroll
            for (int i = 0; i < (BN * 8) / 256; ++i) {
                int idx = tid + i * 256;
                int n = idx >> 3, c4 = (idx & 7) * 4;
                const float4 v = *(const float4*)&B[(long)(bn + n) * ldb + k0 + c4];
                Bs[c4 + 0][n] = f2tf(v.x);
                Bs[c4 + 1][n] = f2tf(v.y);
                Bs[c4 + 2][n] = f2tf(v.z);
                Bs[c4 + 3][n] = f2tf(v.w);
            }
        } else {           // B[k][n] direct
#pragma unroll
            for (int i = 0; i < (32 * BN / 4) / 256; ++i) {
                int idx = tid + i * 256;
                int r = idx / (BN / 4), c4 = (idx % (BN / 4)) * 4;
                const float4 v = *(const float4*)&B[(long)(k0 + r) * ldb + bn + c4];
                uint4 u = make_uint4(f2tf(v.x), f2tf(v.y), f2tf(v.z), f2tf(v.w));
                *(uint4*)&Bs[r][c4] = u;
            }
        }
        __syncthreads();

#pragma unroll
        for (int kb = 0; kb < 32; kb += 8) {
            unsigned af[FM][4], bf[FN][2];
#pragma unroll
            for (int i = 0; i < FM; ++i) {
                int m = mwarp + i * 16 + gid;
                af[i][0] = As[m][kb + tg];
                af[i][1] = As[m + 8][kb + tg];
                af[i][2] = As[m][kb + tg + 4];
                af[i][3] = As[m + 8][kb + tg + 4];
            }
#pragma unroll
            for (int j = 0; j < FN; ++j) {
                int n = nwarp + j * 8 + gid;
                bf[j][0] = Bs[kb + tg][n];
                bf[j][1] = Bs[kb + tg + 4][n];
            }
#pragma unroll
            for (int i = 0; i < FM; ++i)
#pragma unroll
                for (int j = 0; j < FN; ++j)
                    mma_tf32(acc[i][j], af[i][0], af[i][1], af[i][2], af[i][3],
                             bf[j][0], bf[j][1]);
        }
        __syncthreads();
    }

    // ---- epilogue ----
    const float* swp = (FLAGS & 8) ? (swb + (long)zo * swOut) : nullptr;
#pragma unroll
    for (int i = 0; i < FM; ++i) {
        const int r0 = bm + mwarp + i * 16 + gid;
#pragma unroll
        for (int j = 0; j < FN; ++j) {
            const int c = bn + nwarp + j * 8 + tg * 2;
#pragma unroll
            for (int h = 0; h < 2; ++h) {
                const int row = r0 + h * 8;
                float2 p = make_float2(acc[i][j][h * 2], acc[i][j][h * 2 + 1]);
                if (FLAGS & 8) {
                    float2 s = *(const float2*)&swp[(long)row * ldsw + c];
                    p.x = p.x * alpha + s.x;
                    p.y = p.y * alpha + s.y;
                }
                if (FLAGS & 1) { p.x += bias[c]; p.y += bias[c + 1]; }
                if (FLAGS & 2) {
                    p.x = 0.5f * p.x * (1.f + erff(p.x * 0.70710678118654752f));
                    p.y = 0.5f * p.y * (1.f + erff(p.y * 0.70710678118654752f));
                }
                if (FLAGS & 4) {
                    float2 r = *(const float2*)&resid[(long)row * ldres + c];
                    p.x += r.x; p.y += r.y;
                }
                *(float2*)&C[(long)row * ldc + c] = p;
            }
        }
    }
}

// ---------------- launch ------------------------------------------------------
extern "C" void kernel_launch(void* const* d_in, const int* in_sizes, int n_in,
                              void* d_out, int out_size) {
    const float* x_in  = (const float*)d_in[0];
    const float* sw    = (const float*)d_in[1];
    const float* ln1g  = (const float*)d_in[2];
    const float* ln1b  = (const float*)d_in[3];
    const float* wqkv  = (const float*)d_in[4];
    const float* wout  = (const float*)d_in[5];
    const float* bout  = (const float*)d_in[6];
    const float* ln2g  = (const float*)d_in[7];
    const float* ln2b  = (const float*)d_in[8];
    const float* w1    = (const float*)d_in[9];
    const float* b1    = (const float*)d_in[10];
    const float* w2    = (const float*)d_in[11];
    const float* b2    = (const float*)d_in[12];
    float* out = (float*)d_out;

    float *px, *pxn, *pqkv, *psc, *pattn, *ph;
    cudaGetSymbolAddress((void**)&px,    g_x);
    cudaGetSymbolAddress((void**)&pxn,   g_xn);
    cudaGetSymbolAddress((void**)&pqkv,  g_qkv);
    cudaGetSymbolAddress((void**)&psc,   g_sc);
    cudaGetSymbolAddress((void**)&pattn, g_attn);
    cudaGetSymbolAddress((void**)&ph,    g_h);

    const long NN  = (long)N_ * N_;
    const long N3D = (long)N_ * D3;

    for (int l = 0; l < L_; ++l) {
        const float* xcur = (l == 0) ? x_in : px;

        // LN1
        ln_kernel<<<ROWS, 256>>>(xcur, ln1g + (long)l * D_, ln1b + (long)l * D_, pxn);

        // QKV: [4096,768] @ [768,2304]
        gemm_tf32<128,128,0><<<dim3(D3/128, ROWS/128, 1), 256>>>(
            pxn, wqkv + (long)l * D_ * D3, pqkv,
            D_, D_, D3, D3, 0,0,0,0,0,0, 1,
            nullptr, nullptr, 0, nullptr, 0, 0, 0.f);

        // scores = scale * Q K^T + sw  (z = b*H + h, transB)
        gemm_tf32<128,128,8|16><<<dim3(N_/128, N_/128, ZHB), 256>>>(
            pqkv, pqkv + D_, psc,
            DH_, D3, D3, N_,
            N3D, DH_,  N3D, DH_,  (long)H_ * NN, NN,  H_,
            nullptr, nullptr, 0,
            sw, NN, N_, 0.125f);

        // softmax over last dim
        softmax_k<<<ZHB * N_, 256>>>(psc);

        // out = attn @ V  (per-head BN=64)
        gemm_tf32<128,64,0><<<dim3(1, N_/128, ZHB), 256>>>(
            psc, pqkv + 2 * D_, pattn,
            N_, N_, D3, D_,
            (long)H_ * NN, NN,  N3D, DH_,  (long)N_ * D_, DH_,  H_,
            nullptr, nullptr, 0, nullptr, 0, 0, 0.f);

        // proj: attn @ w_out + b_out + x
        gemm_tf32<128,128,1|4><<<dim3(D_/128, ROWS/128, 1), 256>>>(
            pattn, wout + (long)l * D_ * D_, px,
            D_, D_, D_, D_, 0,0,0,0,0,0, 1,
            bout + (long)l * D_, xcur, D_, nullptr, 0, 0, 0.f);

        // LN2
        ln_kernel<<<ROWS, 256>>>(px, ln2g + (long)l * D_, ln2b + (long)l * D_, pxn);

        // FC1 + exact GELU
        gemm_tf32<128,128,1|2><<<dim3(DFF/128, ROWS/128, 1), 256>>>(
            pxn, w1 + (long)l * D_ * DFF, ph,
            D_, D_, DFF, DFF, 0,0,0,0,0,0, 1,
            b1 + (long)l * DFF, nullptr, 0, nullptr, 0, 0, 0.f);

        // FC2 + bias + residual (last layer writes d_out)
        float* cdst = (l == L_ - 1) ? out : px;
        gemm_tf32<128,128,1|4><<<dim3(D_/128, ROWS/128, 1), 256>>>(
            ph, w2 + (long)l * DFF * D_, cdst,
            DFF, DFF, D_, D_, 0,0,0,0,0,0, 1,
            b2 + (long)l * D_, px, D_, nullptr, 0, 0, 0.f);
    }
}

// round 7
// speedup vs baseline: 4.1908x; 1.6848x over previous
#include <cuda_runtime.h>
#include <cuda_fp16.h>
#include <math.h>
#include <stdint.h>

#define D_   768
#define H_   12
#define L_   6
#define B_   4
#define N_   1024
#define DH_  64
#define ROWS (B_*N_)      /* 4096 */
#define D3   (3*D_)       /* 2304 */
#define DFF  (4*D_)       /* 3072 */
#define ZHB  (B_*H_)      /* 48   */

// ---------------- scratch ----------------------------------------------------
__device__ float g_x   [ROWS*(size_t)D_];
__device__ float g_xn  [ROWS*(size_t)D_];
__device__ float g_qkv [ROWS*(size_t)D3];
__device__ float g_sc  [(size_t)ZHB*N_*N_];
__device__ float g_attn[ROWS*(size_t)D_];
__device__ float g_h   [ROWS*(size_t)DFF];

// ---------------- LayerNorm ---------------------------------------------------
__global__ void ln_kernel(const float* __restrict__ x,
                          const float* __restrict__ g,
                          const float* __restrict__ b,
                          float* __restrict__ y) {
    const int row = blockIdx.x;
    const float* xr = x + (size_t)row * D_;
    float*       yr = y + (size_t)row * D_;
    const int tid = threadIdx.x;

    float v[3], s = 0.f, s2 = 0.f;
#pragma unroll
    for (int i = 0; i < 3; ++i) {
        float t = xr[tid + i * 256];
        v[i] = t; s += t; s2 += t * t;
    }
#pragma unroll
    for (int o = 16; o; o >>= 1) {
        s  += __shfl_xor_sync(0xffffffffu, s,  o);
        s2 += __shfl_xor_sync(0xffffffffu, s2, o);
    }
    __shared__ float shs[8], shs2[8];
    const int w = tid >> 5;
    if ((tid & 31) == 0) { shs[w] = s; shs2[w] = s2; }
    __syncthreads();
    s = 0.f; s2 = 0.f;
#pragma unroll
    for (int i = 0; i < 8; ++i) { s += shs[i]; s2 += shs2[i]; }
    const float mean = s * (1.f / D_);
    const float var  = s2 * (1.f / D_) - mean * mean;
    const float rstd = rsqrtf(var + 1e-5f);
#pragma unroll
    for (int i = 0; i < 3; ++i) {
        int c = tid + i * 256;
        yr[c] = (v[i] - mean) * rstd * g[c] + b[c];
    }
}

// ---------------- row softmax over 1024 ---------------------------------------
__global__ void softmax_k(float* __restrict__ sc) {
    const size_t row = blockIdx.x;
    float* p = sc + row * (size_t)N_;
    const int tid = threadIdx.x;

    float v[4], mx = -3.4e38f;
#pragma unroll
    for (int i = 0; i < 4; ++i) { v[i] = p[tid + i * 256]; mx = fmaxf(mx, v[i]); }
#pragma unroll
    for (int o = 16; o; o >>= 1) mx = fmaxf(mx, __shfl_xor_sync(0xffffffffu, mx, o));
    __shared__ float sh[8];
    const int w = tid >> 5;
    if ((tid & 31) == 0) sh[w] = mx;
    __syncthreads();
#pragma unroll
    for (int i = 0; i < 8; ++i) mx = fmaxf(mx, sh[i]);
    __syncthreads();

    float s = 0.f;
#pragma unroll
    for (int i = 0; i < 4; ++i) { v[i] = __expf(v[i] - mx); s += v[i]; }
#pragma unroll
    for (int o = 16; o; o >>= 1) s += __shfl_xor_sync(0xffffffffu, s, o);
    if ((tid & 31) == 0) sh[w] = s;
    __syncthreads();
    s = 0.f;
#pragma unroll
    for (int i = 0; i < 8; ++i) s += sh[i];
    const float r = 1.f / s;
#pragma unroll
    for (int i = 0; i < 4; ++i) p[tid + i * 256] = v[i] * r;
}

// ---------------- fp16 tensor-core GEMM ---------------------------------------
__device__ __forceinline__ unsigned pack2(float x, float y) {
    __half2 h = __floats2half2_rn(x, y);
    return *reinterpret_cast<unsigned*>(&h);
}
__device__ __forceinline__ void mma_f16(float* c,
                                        unsigned a0, unsigned a1, unsigned a2, unsigned a3,
                                        unsigned b0, unsigned b1) {
    asm volatile(
        "mma.sync.aligned.m16n8k16.row.col.f32.f16.f16.f32 "
        "{%0,%1,%2,%3}, {%4,%5,%6,%7}, {%8,%9}, {%0,%1,%2,%3};"
        : "+f"(c[0]), "+f"(c[1]), "+f"(c[2]), "+f"(c[3])
        : "r"(a0), "r"(a1), "r"(a2), "r"(a3), "r"(b0), "r"(b1));
}

// FLAGS: 1=bias 2=gelu(exact) 4=residual 8=alpha*acc+spatial-bias 16=transB
// BM=128, 256 threads, 8 warps as 2(m) x 4(n); warp tile 64 x (BN/4); BK=32.
// A,B staged in k-major half smem (row stride 40 halfs, 80B rows).
template<int BN, int FLAGS>
__global__ void __launch_bounds__(256, 2)
gemm_h(const float* __restrict__ A, const float* __restrict__ B,
       float* __restrict__ C,
       int K, int lda, int ldb, int ldc,
       long aOut, long aIn, long bOut, long bIn, long cOut, long cIn, int zdiv,
       const float* __restrict__ bias,
       const float* __restrict__ resid, int ldres,
       const float* __restrict__ swb, long swOut, int ldsw,
       float alpha) {
    constexpr int BM = 128;
    constexpr int FM = 4;           // 4 m-frags of 16 rows (warp tile m = 64)
    constexpr int FN = BN / 32;     // n-frags of 8 cols   (warp tile n = BN/4)
    constexpr int SK = 40;          // smem k stride in halfs (80B rows)

    __shared__ __half As[BM][SK];
    __shared__ __half Bs[BN][SK];

    const int tid  = threadIdx.x;
    const int lane = tid & 31;
    const int gid  = lane >> 2;
    const int tg   = lane & 3;
    const int warp = tid >> 5;
    const int wm   = warp >> 2;          // 0..1
    const int wn   = warp & 3;           // 0..3
    const int mwarp = wm * 64;
    const int nwarp = wn * (BN / 4);

    const int bn = blockIdx.x * BN;
    const int bm = blockIdx.y * BM;
    const int z  = blockIdx.z;
    const int zo = z / zdiv, zi = z - zo * zdiv;
    A += zo * aOut + zi * aIn;
    B += zo * bOut + zi * bIn;
    C += zo * cOut + zi * cIn;

    float acc[FM][FN][4] = {};

    for (int k0 = 0; k0 < K; k0 += 32) {
        // ---- A tile: As[m][k], float4 along k ----
#pragma unroll
        for (int i = 0; i < 4; ++i) {
            int flat = tid + i * 256;           // over 128 x 8 (m, k4)
            int m = flat >> 3, k4 = (flat & 7) * 4;
            const float4 v = *(const float4*)&A[(long)(bm + m) * lda + k0 + k4];
            *(uint2*)&As[m][k4] = make_uint2(pack2(v.x, v.y), pack2(v.z, v.w));
        }
        // ---- B tile: Bs[n][k] ----
        if (FLAGS & 16) {   // B global [n][k]
#pragma unroll
            for (int i = 0; i < BN / 32; ++i) {
                int flat = tid + i * 256;       // over BN x 8
                int n = flat >> 3, k4 = (flat & 7) * 4;
                const float4 v = *(const float4*)&B[(long)(bn + n) * ldb + k0 + k4];
                *(uint2*)&Bs[n][k4] = make_uint2(pack2(v.x, v.y), pack2(v.z, v.w));
            }
        } else {            // B global [k][n]: per-thread column gather
            constexpr int CNT = BN / 8;         // k-span per thread
            const int n  = tid & (BN - 1);
            const int kb = (tid / BN) * CNT;
            const float* Bp = B + (long)(k0 + kb) * ldb + bn + n;
            float t[CNT];
#pragma unroll
            for (int k = 0; k < CNT; ++k) t[k] = Bp[(long)k * ldb];
#pragma unroll
            for (int k = 0; k < CNT; k += 8) {
                *(uint4*)&Bs[n][kb + k] = make_uint4(
                    pack2(t[k+0], t[k+1]), pack2(t[k+2], t[k+3]),
                    pack2(t[k+4], t[k+5]), pack2(t[k+6], t[k+7]));
            }
        }
        __syncthreads();

#pragma unroll
        for (int ks = 0; ks < 2; ++ks) {
            const int kb2 = ks * 16 + tg * 2;
            unsigned af[FM][4], bf[FN][2];
#pragma unroll
            for (int i = 0; i < FM; ++i) {
                int m0 = mwarp + i * 16 + gid;
                af[i][0] = *(const unsigned*)&As[m0][kb2];
                af[i][1] = *(const unsigned*)&As[m0 + 8][kb2];
                af[i][2] = *(const unsigned*)&As[m0][kb2 + 8];
                af[i][3] = *(const unsigned*)&As[m0 + 8][kb2 + 8];
            }
#pragma unroll
            for (int j = 0; j < FN; ++j) {
                int n = nwarp + j * 8 + gid;
                bf[j][0] = *(const unsigned*)&Bs[n][kb2];
                bf[j][1] = *(const unsigned*)&Bs[n][kb2 + 8];
            }
#pragma unroll
            for (int i = 0; i < FM; ++i)
#pragma unroll
                for (int j = 0; j < FN; ++j)
                    mma_f16(acc[i][j], af[i][0], af[i][1], af[i][2], af[i][3],
                            bf[j][0], bf[j][1]);
        }
        __syncthreads();
    }

    // ---- epilogue ----
    const float* swp = (FLAGS & 8) ? (swb + (long)zo * swOut) : nullptr;
#pragma unroll
    for (int i = 0; i < FM; ++i) {
        const int r0 = bm + mwarp + i * 16 + gid;
#pragma unroll
        for (int j = 0; j < FN; ++j) {
            const int c = bn + nwarp + j * 8 + tg * 2;
#pragma unroll
            for (int h = 0; h < 2; ++h) {
                const int row = r0 + h * 8;
                float2 p = make_float2(acc[i][j][h * 2], acc[i][j][h * 2 + 1]);
                if (FLAGS & 8) {
                    float2 s = *(const float2*)&swp[(long)row * ldsw + c];
                    p.x = p.x * alpha + s.x;
                    p.y = p.y * alpha + s.y;
                }
                if (FLAGS & 1) { p.x += bias[c]; p.y += bias[c + 1]; }
                if (FLAGS & 2) {
                    p.x = 0.5f * p.x * (1.f + erff(p.x * 0.70710678118654752f));
                    p.y = 0.5f * p.y * (1.f + erff(p.y * 0.70710678118654752f));
                }
                if (FLAGS & 4) {
                    float2 r = *(const float2*)&resid[(long)row * ldres + c];
                    p.x += r.x; p.y += r.y;
                }
                *(float2*)&C[(long)row * ldc + c] = p;
            }
        }
    }
}

// ---------------- launch ------------------------------------------------------
extern "C" void kernel_launch(void* const* d_in, const int* in_sizes, int n_in,
                              void* d_out, int out_size) {
    const float* x_in  = (const float*)d_in[0];
    const float* sw    = (const float*)d_in[1];
    const float* ln1g  = (const float*)d_in[2];
    const float* ln1b  = (const float*)d_in[3];
    const float* wqkv  = (const float*)d_in[4];
    const float* wout  = (const float*)d_in[5];
    const float* bout  = (const float*)d_in[6];
    const float* ln2g  = (const float*)d_in[7];
    const float* ln2b  = (const float*)d_in[8];
    const float* w1    = (const float*)d_in[9];
    const float* b1    = (const float*)d_in[10];
    const float* w2    = (const float*)d_in[11];
    const float* b2    = (const float*)d_in[12];
    float* out = (float*)d_out;

    float *px, *pxn, *pqkv, *psc, *pattn, *ph;
    cudaGetSymbolAddress((void**)&px,    g_x);
    cudaGetSymbolAddress((void**)&pxn,   g_xn);
    cudaGetSymbolAddress((void**)&pqkv,  g_qkv);
    cudaGetSymbolAddress((void**)&psc,   g_sc);
    cudaGetSymbolAddress((void**)&pattn, g_attn);
    cudaGetSymbolAddress((void**)&ph,    g_h);

    const long NN  = (long)N_ * N_;
    const long N3D = (long)N_ * D3;

    for (int l = 0; l < L_; ++l) {
        const float* xcur = (l == 0) ? x_in : px;

        // LN1
        ln_kernel<<<ROWS, 256>>>(xcur, ln1g + (long)l * D_, ln1b + (long)l * D_, pxn);

        // QKV: [4096,768] @ [768,2304]
        gemm_h<128,0><<<dim3(D3/128, ROWS/128, 1), 256>>>(
            pxn, wqkv + (long)l * D_ * D3, pqkv,
            D_, D_, D3, D3, 0,0,0,0,0,0, 1,
            nullptr, nullptr, 0, nullptr, 0, 0, 0.f);

        // scores = scale * Q K^T + sw  (z = b*H + h, transB)
        gemm_h<128,8|16><<<dim3(N_/128, N_/128, ZHB), 256>>>(
            pqkv, pqkv + D_, psc,
            DH_, D3, D3, N_,
            N3D, DH_,  N3D, DH_,  (long)H_ * NN, NN,  H_,
            nullptr, nullptr, 0,
            sw, NN, N_, 0.125f);

        // softmax
        softmax_k<<<ZHB * N_, 256>>>(psc);

        // out = attn @ V  (per-head, BN=64)
        gemm_h<64,0><<<dim3(1, N_/128, ZHB), 256>>>(
            psc, pqkv + 2 * D_, pattn,
            N_, N_, D3, D_,
            (long)H_ * NN, NN,  N3D, DH_,  (long)N_ * D_, DH_,  H_,
            nullptr, nullptr, 0, nullptr, 0, 0, 0.f);

        // proj + bias + residual
        gemm_h<128,1|4><<<dim3(D_/128, ROWS/128, 1), 256>>>(
            pattn, wout + (long)l * D_ * D_, px,
            D_, D_, D_, D_, 0,0,0,0,0,0, 1,
            bout + (long)l * D_, xcur, D_, nullptr, 0, 0, 0.f);

        // LN2
        ln_kernel<<<ROWS, 256>>>(px, ln2g + (long)l * D_, ln2b + (long)l * D_, pxn);

        // FC1 + bias + GELU   (w1 is [768,3072] -> ldb = DFF)
        gemm_h<128,1|2><<<dim3(DFF/128, ROWS/128, 1), 256>>>(
            pxn, w1 + (long)l * D_ * DFF, ph,
            D_, D_, DFF, DFF, 0,0,0,0,0,0, 1,
            b1 + (long)l * DFF, nullptr, 0, nullptr, 0, 0, 0.f);

        // FC2 + bias + residual (w2 is [3072,768] -> ldb = D_; last layer -> d_out)
        float* cdst = (l == L_ - 1) ? out : px;
        gemm_h<128,1|4><<<dim3(D_/128, ROWS/128, 1), 256>>>(
            ph, w2 + (long)l * DFF * D_, cdst,
            DFF, DFF, D_, D_, 0,0,0,0,0,0, 1,
            b2 + (long)l * D_, px, D_, nullptr, 0, 0, 0.f);
    }
}

// round 8
// speedup vs baseline: 5.1150x; 1.2205x over previous
#include <cuda_runtime.h>
#include <cuda_fp16.h>
#include <math.h>
#include <stdint.h>

#define D_   768
#define H_   12
#define L_   6
#define B_   4
#define N_   1024
#define DH_  64
#define ROWS (B_*N_)      /* 4096 */
#define D3   (3*D_)       /* 2304 */
#define DFF  (4*D_)       /* 3072 */
#define ZHB  (B_*H_)      /* 48   */

// ---------------- scratch ----------------------------------------------------
__device__ float g_x   [ROWS*(size_t)D_];
__device__ float g_xn  [ROWS*(size_t)D_];
__device__ float g_qkv [ROWS*(size_t)D3];
__device__ float g_attn[ROWS*(size_t)D_];
__device__ float g_h   [ROWS*(size_t)DFF];

// ---------------- LayerNorm ---------------------------------------------------
__global__ void ln_kernel(const float* __restrict__ x,
                          const float* __restrict__ g,
                          const float* __restrict__ b,
                          float* __restrict__ y) {
    const int row = blockIdx.x;
    const float* xr = x + (size_t)row * D_;
    float*       yr = y + (size_t)row * D_;
    const int tid = threadIdx.x;

    float v[3], s = 0.f, s2 = 0.f;
#pragma unroll
    for (int i = 0; i < 3; ++i) {
        float t = xr[tid + i * 256];
        v[i] = t; s += t; s2 += t * t;
    }
#pragma unroll
    for (int o = 16; o; o >>= 1) {
        s  += __shfl_xor_sync(0xffffffffu, s,  o);
        s2 += __shfl_xor_sync(0xffffffffu, s2, o);
    }
    __shared__ float shs[8], shs2[8];
    const int w = tid >> 5;
    if ((tid & 31) == 0) { shs[w] = s; shs2[w] = s2; }
    __syncthreads();
    s = 0.f; s2 = 0.f;
#pragma unroll
    for (int i = 0; i < 8; ++i) { s += shs[i]; s2 += shs2[i]; }
    const float mean = s * (1.f / D_);
    const float var  = s2 * (1.f / D_) - mean * mean;
    const float rstd = rsqrtf(var + 1e-5f);
#pragma unroll
    for (int i = 0; i < 3; ++i) {
        int c = tid + i * 256;
        yr[c] = (v[i] - mean) * rstd * g[c] + b[c];
    }
}

// ---------------- fp16 mma helpers --------------------------------------------
__device__ __forceinline__ unsigned pack2(float x, float y) {
    __half2 h = __floats2half2_rn(x, y);
    return *reinterpret_cast<unsigned*>(&h);
}
__device__ __forceinline__ void mma_f16(float* c,
                                        unsigned a0, unsigned a1, unsigned a2, unsigned a3,
                                        unsigned b0, unsigned b1) {
    asm volatile(
        "mma.sync.aligned.m16n8k16.row.col.f32.f16.f16.f32 "
        "{%0,%1,%2,%3}, {%4,%5,%6,%7}, {%8,%9}, {%0,%1,%2,%3};"
        : "+f"(c[0]), "+f"(c[1]), "+f"(c[2]), "+f"(c[3])
        : "r"(a0), "r"(a1), "r"(a2), "r"(a3), "r"(b0), "r"(b1));
}

// ---------------- fused flash attention ---------------------------------------
// grid (N/128, ZHB), 256 threads (8 warps; warp w owns 16 query rows).
// Q pre-scaled by 1/8. S accumulated fp32; online softmax; P.V via frag reuse.
#define FL_SMEM (2*128*72*2 + 64*136*2)   /* Qs + Ks + Vs = 54272 bytes */
__global__ void __launch_bounds__(256)
flash_k(const float* __restrict__ qkv, const float* __restrict__ sw,
        float* __restrict__ outp) {
    extern __shared__ __half sm[];
    __half (*Qs)[72]  = (__half(*)[72])  sm;
    __half (*Ks)[72]  = (__half(*)[72])  (sm + 128 * 72);
    __half (*Vs)[136] = (__half(*)[136]) (sm + 2 * 128 * 72);

    const int tid = threadIdx.x, lane = tid & 31;
    const int gid = lane >> 2, tg = lane & 3;
    const int warp = tid >> 5;
    const int m0 = warp * 16;
    const int bm = blockIdx.x * 128;
    const int z = blockIdx.y, b = z / H_, h = z - b * H_;

    const float* Qg = qkv + ((long)(b * N_ + bm)) * D3 + h * DH_;
    const float* Kg = qkv + (long)b * N_ * D3 + D_ + h * DH_;
    const float* Vg = Kg + D_;
    const float* swb = sw + (long)b * N_ * N_;

    // ---- load Q tile (scaled by 1/8) ----
#pragma unroll
    for (int i = 0; i < 8; ++i) {
        int flat = tid + i * 256;
        int r = flat >> 4, c4 = (flat & 15) * 4;
        float4 v = *(const float4*)&Qg[(long)r * D3 + c4];
        *(uint2*)&Qs[r][c4] = make_uint2(pack2(v.x * 0.125f, v.y * 0.125f),
                                         pack2(v.z * 0.125f, v.w * 0.125f));
    }

    float m0r = -3.4e38f, m1r = -3.4e38f, l0 = 0.f, l1 = 0.f;
    float oacc[8][4];
#pragma unroll
    for (int jo = 0; jo < 8; ++jo)
#pragma unroll
        for (int q = 0; q < 4; ++q) oacc[jo][q] = 0.f;

    for (int kv0 = 0; kv0 < N_; kv0 += 128) {
        __syncthreads();
        // ---- K tile ----
#pragma unroll
        for (int i = 0; i < 8; ++i) {
            int flat = tid + i * 256;
            int r = flat >> 4, c4 = (flat & 15) * 4;
            float4 v = *(const float4*)&Kg[(long)(kv0 + r) * D3 + c4];
            *(uint2*)&Ks[r][c4] = make_uint2(pack2(v.x, v.y), pack2(v.z, v.w));
        }
        // ---- V tile, transposed to Vs[dim][token] ----
#pragma unroll
        for (int i = 0; i < 8; ++i) {
            int flat = tid + i * 256;
            int r = flat >> 4, c4 = (flat & 15) * 4;
            float4 v = *(const float4*)&Vg[(long)(kv0 + r) * D3 + c4];
            Vs[c4 + 0][r] = __float2half(v.x);
            Vs[c4 + 1][r] = __float2half(v.y);
            Vs[c4 + 2][r] = __float2half(v.z);
            Vs[c4 + 3][r] = __float2half(v.w);
        }
        __syncthreads();

        // ---- S = Q K^T (fp32 accum) ----
        float acc[16][4];
#pragma unroll
        for (int j = 0; j < 16; ++j)
#pragma unroll
            for (int q = 0; q < 4; ++q) acc[j][q] = 0.f;
#pragma unroll
        for (int kt = 0; kt < 4; ++kt) {
            const int kb = kt * 16 + tg * 2;
            unsigned a0 = *(const unsigned*)&Qs[m0 + gid][kb];
            unsigned a1 = *(const unsigned*)&Qs[m0 + gid + 8][kb];
            unsigned a2 = *(const unsigned*)&Qs[m0 + gid][kb + 8];
            unsigned a3 = *(const unsigned*)&Qs[m0 + gid + 8][kb + 8];
#pragma unroll
            for (int j = 0; j < 16; ++j) {
                unsigned b0 = *(const unsigned*)&Ks[j * 8 + gid][kb];
                unsigned b1 = *(const unsigned*)&Ks[j * 8 + gid][kb + 8];
                mma_f16(acc[j], a0, a1, a2, a3, b0, b1);
            }
        }

        // ---- + spatial bias; row max ----
        const float* sw0 = swb + (long)(bm + m0 + gid) * N_ + kv0;
        const float* sw1 = sw0 + 8 * N_;
        float mx0 = -3.4e38f, mx1 = -3.4e38f;
#pragma unroll
        for (int j = 0; j < 16; ++j) {
            float2 s0 = *(const float2*)&sw0[j * 8 + tg * 2];
            float2 s1 = *(const float2*)&sw1[j * 8 + tg * 2];
            acc[j][0] += s0.x; acc[j][1] += s0.y;
            acc[j][2] += s1.x; acc[j][3] += s1.y;
            mx0 = fmaxf(mx0, fmaxf(acc[j][0], acc[j][1]));
            mx1 = fmaxf(mx1, fmaxf(acc[j][2], acc[j][3]));
        }
#pragma unroll
        for (int o = 1; o <= 2; o <<= 1) {
            mx0 = fmaxf(mx0, __shfl_xor_sync(0xffffffffu, mx0, o));
            mx1 = fmaxf(mx1, __shfl_xor_sync(0xffffffffu, mx1, o));
        }

        const float mn0 = fmaxf(m0r, mx0), mn1 = fmaxf(m1r, mx1);
        const float sc0 = __expf(m0r - mn0), sc1 = __expf(m1r - mn1);
        m0r = mn0; m1r = mn1;

        // ---- P = exp(S - m); pack to A-frags; row sums ----
        float rs0 = 0.f, rs1 = 0.f;
        unsigned pr[16][2];
#pragma unroll
        for (int j = 0; j < 16; ++j) {
            float p0 = __expf(acc[j][0] - mn0);
            float p1 = __expf(acc[j][1] - mn0);
            float p2 = __expf(acc[j][2] - mn1);
            float p3 = __expf(acc[j][3] - mn1);
            rs0 += p0 + p1; rs1 += p2 + p3;
            pr[j][0] = pack2(p0, p1);
            pr[j][1] = pack2(p2, p3);
        }
#pragma unroll
        for (int o = 1; o <= 2; o <<= 1) {
            rs0 += __shfl_xor_sync(0xffffffffu, rs0, o);
            rs1 += __shfl_xor_sync(0xffffffffu, rs1, o);
        }
        l0 = l0 * sc0 + rs0;
        l1 = l1 * sc1 + rs1;

        // ---- O = O*scale + P.V ----
#pragma unroll
        for (int jo = 0; jo < 8; ++jo) {
            oacc[jo][0] *= sc0; oacc[jo][1] *= sc0;
            oacc[jo][2] *= sc1; oacc[jo][3] *= sc1;
        }
#pragma unroll
        for (int kt2 = 0; kt2 < 8; ++kt2) {
            unsigned a0 = pr[2 * kt2][0],     a1 = pr[2 * kt2][1];
            unsigned a2 = pr[2 * kt2 + 1][0], a3 = pr[2 * kt2 + 1][1];
            const int kb = kt2 * 16 + tg * 2;
#pragma unroll
            for (int jo = 0; jo < 8; ++jo) {
                unsigned b0 = *(const unsigned*)&Vs[jo * 8 + gid][kb];
                unsigned b1 = *(const unsigned*)&Vs[jo * 8 + gid][kb + 8];
                mma_f16(oacc[jo], a0, a1, a2, a3, b0, b1);
            }
        }
    }

    // ---- write O / l ----
    const float i0 = 1.f / l0, i1 = 1.f / l1;
    float* o0 = outp + (long)(b * N_ + bm + m0 + gid) * D_ + h * DH_;
    float* o1 = o0 + 8 * D_;
#pragma unroll
    for (int jo = 0; jo < 8; ++jo) {
        *(float2*)&o0[jo * 8 + tg * 2] = make_float2(oacc[jo][0] * i0, oacc[jo][1] * i0);
        *(float2*)&o1[jo * 8 + tg * 2] = make_float2(oacc[jo][2] * i1, oacc[jo][3] * i1);
    }
}

// ---------------- fp16 tensor-core GEMM (dense path) --------------------------
// FLAGS: 1=bias 2=gelu(exact) 4=residual
template<int BN, int FLAGS>
__global__ void __launch_bounds__(256, 2)
gemm_h(const float* __restrict__ A, const float* __restrict__ B,
       float* __restrict__ C,
       int K, int lda, int ldb, int ldc,
       const float* __restrict__ bias,
       const float* __restrict__ resid, int ldres) {
    constexpr int BM = 128;
    constexpr int FM = 4;
    constexpr int FN = BN / 32;
    constexpr int SK = 40;

    __shared__ __half As[BM][SK];
    __shared__ __half Bs[BN][SK];

    const int tid  = threadIdx.x;
    const int lane = tid & 31;
    const int gid  = lane >> 2;
    const int tg   = lane & 3;
    const int warp = tid >> 5;
    const int wm   = warp >> 2;
    const int wn   = warp & 3;
    const int mwarp = wm * 64;
    const int nwarp = wn * (BN / 4);

    const int bn = blockIdx.x * BN;
    const int bm = blockIdx.y * BM;

    float acc[FM][FN][4] = {};

    for (int k0 = 0; k0 < K; k0 += 32) {
#pragma unroll
        for (int i = 0; i < 4; ++i) {
            int flat = tid + i * 256;
            int m = flat >> 3, k4 = (flat & 7) * 4;
            const float4 v = *(const float4*)&A[(long)(bm + m) * lda + k0 + k4];
            *(uint2*)&As[m][k4] = make_uint2(pack2(v.x, v.y), pack2(v.z, v.w));
        }
        {   // B global [k][n]: per-thread column gather
            constexpr int CNT = BN / 8;
            const int n  = tid & (BN - 1);
            const int kb = (tid / BN) * CNT;
            const float* Bp = B + (long)(k0 + kb) * ldb + bn + n;
            float t[CNT];
#pragma unroll
            for (int k = 0; k < CNT; ++k) t[k] = Bp[(long)k * ldb];
#pragma unroll
            for (int k = 0; k < CNT; k += 8) {
                *(uint4*)&Bs[n][kb + k] = make_uint4(
                    pack2(t[k+0], t[k+1]), pack2(t[k+2], t[k+3]),
                    pack2(t[k+4], t[k+5]), pack2(t[k+6], t[k+7]));
            }
        }
        __syncthreads();

#pragma unroll
        for (int ks = 0; ks < 2; ++ks) {
            const int kb2 = ks * 16 + tg * 2;
            unsigned af[FM][4], bf[FN][2];
#pragma unroll
            for (int i = 0; i < FM; ++i) {
                int mm = mwarp + i * 16 + gid;
                af[i][0] = *(const unsigned*)&As[mm][kb2];
                af[i][1] = *(const unsigned*)&As[mm + 8][kb2];
                af[i][2] = *(const unsigned*)&As[mm][kb2 + 8];
                af[i][3] = *(const unsigned*)&As[mm + 8][kb2 + 8];
            }
#pragma unroll
            for (int j = 0; j < FN; ++j) {
                int n = nwarp + j * 8 + gid;
                bf[j][0] = *(const unsigned*)&Bs[n][kb2];
                bf[j][1] = *(const unsigned*)&Bs[n][kb2 + 8];
            }
#pragma unroll
            for (int i = 0; i < FM; ++i)
#pragma unroll
                for (int j = 0; j < FN; ++j)
                    mma_f16(acc[i][j], af[i][0], af[i][1], af[i][2], af[i][3],
                            bf[j][0], bf[j][1]);
        }
        __syncthreads();
    }

#pragma unroll
    for (int i = 0; i < FM; ++i) {
        const int r0 = bm + mwarp + i * 16 + gid;
#pragma unroll
        for (int j = 0; j < FN; ++j) {
            const int c = bn + nwarp + j * 8 + tg * 2;
#pragma unroll
            for (int hh = 0; hh < 2; ++hh) {
                const int row = r0 + hh * 8;
                float2 p = make_float2(acc[i][j][hh * 2], acc[i][j][hh * 2 + 1]);
                if (FLAGS & 1) { p.x += bias[c]; p.y += bias[c + 1]; }
                if (FLAGS & 2) {
                    p.x = 0.5f * p.x * (1.f + erff(p.x * 0.70710678118654752f));
                    p.y = 0.5f * p.y * (1.f + erff(p.y * 0.70710678118654752f));
                }
                if (FLAGS & 4) {
                    float2 r = *(const float2*)&resid[(long)row * ldres + c];
                    p.x += r.x; p.y += r.y;
                }
                *(float2*)&C[(long)row * ldc + c] = p;
            }
        }
    }
}

// ---------------- launch ------------------------------------------------------
extern "C" void kernel_launch(void* const* d_in, const int* in_sizes, int n_in,
                              void* d_out, int out_size) {
    const float* x_in  = (const float*)d_in[0];
    const float* sw    = (const float*)d_in[1];
    const float* ln1g  = (const float*)d_in[2];
    const float* ln1b  = (const float*)d_in[3];
    const float* wqkv  = (const float*)d_in[4];
    const float* wout  = (const float*)d_in[5];
    const float* bout  = (const float*)d_in[6];
    const float* ln2g  = (const float*)d_in[7];
    const float* ln2b  = (const float*)d_in[8];
    const float* w1    = (const float*)d_in[9];
    const float* b1    = (const float*)d_in[10];
    const float* w2    = (const float*)d_in[11];
    const float* b2    = (const float*)d_in[12];
    float* out = (float*)d_out;

    float *px, *pxn, *pqkv, *pattn, *ph;
    cudaGetSymbolAddress((void**)&px,    g_x);
    cudaGetSymbolAddress((void**)&pxn,   g_xn);
    cudaGetSymbolAddress((void**)&pqkv,  g_qkv);
    cudaGetSymbolAddress((void**)&pattn, g_attn);
    cudaGetSymbolAddress((void**)&ph,    g_h);

    cudaFuncSetAttribute(flash_k, cudaFuncAttributeMaxDynamicSharedMemorySize, FL_SMEM);

    for (int l = 0; l < L_; ++l) {
        const float* xcur = (l == 0) ? x_in : px;

        // LN1
        ln_kernel<<<ROWS, 256>>>(xcur, ln1g + (long)l * D_, ln1b + (long)l * D_, pxn);

        // QKV: [4096,768] @ [768,2304]
        gemm_h<128,0><<<dim3(D3/128, ROWS/128), 256>>>(
            pxn, wqkv + (long)l * D_ * D3, pqkv,
            D_, D_, D3, D3, nullptr, nullptr, 0);

        // fused attention: scores + bias + softmax + P.V
        flash_k<<<dim3(N_/128, ZHB), 256, FL_SMEM>>>(pqkv, sw, pattn);

        // proj + bias + residual
        gemm_h<128,1|4><<<dim3(D_/128, ROWS/128), 256>>>(
            pattn, wout + (long)l * D_ * D_, px,
            D_, D_, D_, D_,
            bout + (long)l * D_, xcur, D_);

        // LN2
        ln_kernel<<<ROWS, 256>>>(px, ln2g + (long)l * D_, ln2b + (long)l * D_, pxn);

        // FC1 + bias + GELU  (w1 [768,3072], ldb=DFF)
        gemm_h<128,1|2><<<dim3(DFF/128, ROWS/128), 256>>>(
            pxn, w1 + (long)l * D_ * DFF, ph,
            D_, D_, DFF, DFF,
            b1 + (long)l * DFF, nullptr, 0);

        // FC2 + bias + residual (w2 [3072,768], ldb=D_; last layer -> d_out)
        float* cdst = (l == L_ - 1) ? out : px;
        gemm_h<128,1|4><<<dim3(D_/128, ROWS/128), 256>>>(
            ph, w2 + (long)l * DFF * D_, cdst,
            DFF, DFF, D_, D_,
            b2 + (long)l * D_, px, D_);
    }
}

// round 9
// speedup vs baseline: 5.4934x; 1.0740x over previous
#include <cuda_runtime.h>
#include <cuda_fp16.h>
#include <math.h>
#include <stdint.h>

#define D_   768
#define H_   12
#define L_   6
#define B_   4
#define N_   1024
#define DH_  64
#define ROWS (B_*N_)      /* 4096 */
#define D3   (3*D_)       /* 2304 */
#define DFF  (4*D_)       /* 3072 */
#define ZHB  (B_*H_)      /* 48   */

// transposed fp16 weight offsets (halfs, per layer)
#define OFF_QKVT 0
#define OFF_OWT  (768*2304)
#define OFF_W1T  (OFF_OWT + 768*768)
#define OFF_W2T  (OFF_W1T + 768*3072)
#define WT_LSTR  (OFF_W2T + 3072*768)   /* 7077888 */

// ---------------- scratch ----------------------------------------------------
__device__ float  g_x   [ROWS*(size_t)D_];
__device__ __half g_xnh [ROWS*(size_t)D_];
__device__ __half g_qkvh[ROWS*(size_t)D3];
__device__ __half g_atth[ROWS*(size_t)D_];
__device__ __half g_hh  [ROWS*(size_t)DFF];
__device__ __half g_whT [(size_t)L_*WT_LSTR];

__device__ __forceinline__ unsigned pack2(float x, float y) {
    __half2 h = __floats2half2_rn(x, y);
    return *reinterpret_cast<unsigned*>(&h);
}
__device__ __forceinline__ void mma_f16(float* c,
                                        unsigned a0, unsigned a1, unsigned a2, unsigned a3,
                                        unsigned b0, unsigned b1) {
    asm volatile(
        "mma.sync.aligned.m16n8k16.row.col.f32.f16.f16.f32 "
        "{%0,%1,%2,%3}, {%4,%5,%6,%7}, {%8,%9}, {%0,%1,%2,%3};"
        : "+f"(c[0]), "+f"(c[1]), "+f"(c[2]), "+f"(c[3])
        : "r"(a0), "r"(a1), "r"(a2), "r"(a3), "r"(b0), "r"(b1));
}
__device__ __forceinline__ uint32_t smem_u32(const void* p) {
    uint32_t a;
    asm("{ .reg .u64 t; cvta.to.shared.u64 t, %1; cvt.u32.u64 %0, t; }" : "=r"(a) : "l"(p));
    return a;
}

// ---------------- weight transpose+cvt: src fp32 [R,C] -> dst fp16 [C,R] ------
__global__ void tr_h(const float* __restrict__ src, __half* __restrict__ dst,
                     int R, int C) {
    __shared__ float t[32][33];
    const int c0 = blockIdx.x * 32, r0 = blockIdx.y * 32;
    const int x = threadIdx.x, y = threadIdx.y;
#pragma unroll
    for (int i = 0; i < 32; i += 8)
        t[y + i][x] = src[(long)(r0 + y + i) * C + c0 + x];
    __syncthreads();
#pragma unroll
    for (int i = 0; i < 32; i += 8)
        dst[(long)(c0 + y + i) * R + r0 + x] = __float2half(t[x][y + i]);
}

// ---------------- LayerNorm (fp32 in, fp16 out) --------------------------------
__global__ void ln_kernel(const float* __restrict__ x,
                          const float* __restrict__ g,
                          const float* __restrict__ b,
                          __half* __restrict__ y) {
    const int row = blockIdx.x;
    const float* xr = x + (size_t)row * D_;
    __half*      yr = y + (size_t)row * D_;
    const int tid = threadIdx.x;

    float v[3], s = 0.f, s2 = 0.f;
#pragma unroll
    for (int i = 0; i < 3; ++i) {
        float t = xr[tid + i * 256];
        v[i] = t; s += t; s2 += t * t;
    }
#pragma unroll
    for (int o = 16; o; o >>= 1) {
        s  += __shfl_xor_sync(0xffffffffu, s,  o);
        s2 += __shfl_xor_sync(0xffffffffu, s2, o);
    }
    __shared__ float shs[8], shs2[8];
    const int w = tid >> 5;
    if ((tid & 31) == 0) { shs[w] = s; shs2[w] = s2; }
    __syncthreads();
    s = 0.f; s2 = 0.f;
#pragma unroll
    for (int i = 0; i < 8; ++i) { s += shs[i]; s2 += shs2[i]; }
    const float mean = s * (1.f / D_);
    const float var  = s2 * (1.f / D_) - mean * mean;
    const float rstd = rsqrtf(var + 1e-5f);
#pragma unroll
    for (int i = 0; i < 3; ++i) {
        int c = tid + i * 256;
        yr[c] = __float2half((v[i] - mean) * rstd * g[c] + b[c]);
    }
}

// ---------------- fused flash attention (fp16 qkv in, fp16 out) ---------------
#define FL_SMEM (2*128*72*2 + 64*136*2)
__global__ void __launch_bounds__(256)
flash_k(const __half* __restrict__ qkv, const float* __restrict__ sw,
        __half* __restrict__ outp) {
    extern __shared__ __half sm[];
    __half (*Qs)[72]  = (__half(*)[72])  sm;
    __half (*Ks)[72]  = (__half(*)[72])  (sm + 128 * 72);
    __half (*Vs)[136] = (__half(*)[136]) (sm + 2 * 128 * 72);

    const int tid = threadIdx.x, lane = tid & 31;
    const int gid = lane >> 2, tg = lane & 3;
    const int warp = tid >> 5;
    const int m0 = warp * 16;
    const int bm = blockIdx.x * 128;
    const int z = blockIdx.y, b = z / H_, h = z - b * H_;

    const __half* Qg = qkv + ((long)(b * N_ + bm)) * D3 + h * DH_;
    const __half* Kg = qkv + (long)b * N_ * D3 + D_ + h * DH_;
    const __half* Vg = Kg + D_;
    const float* swb = sw + (long)b * N_ * N_;

    // ---- Q tile (already pre-scaled by 1/8 in QKV epilogue) ----
#pragma unroll
    for (int i = 0; i < 4; ++i) {
        int flat = tid + i * 256;
        int r = flat >> 3, j = (flat & 7) * 8;
        *(uint4*)&Qs[r][j] = *(const uint4*)&Qg[(long)r * D3 + j];
    }

    float m0r = -3.4e38f, m1r = -3.4e38f, l0 = 0.f, l1 = 0.f;
    float oacc[8][4];
#pragma unroll
    for (int jo = 0; jo < 8; ++jo)
#pragma unroll
        for (int q = 0; q < 4; ++q) oacc[jo][q] = 0.f;

    for (int kv0 = 0; kv0 < N_; kv0 += 128) {
        __syncthreads();
#pragma unroll
        for (int i = 0; i < 4; ++i) {
            int flat = tid + i * 256;
            int r = flat >> 3, j = (flat & 7) * 8;
            *(uint4*)&Ks[r][j] = *(const uint4*)&Kg[(long)(kv0 + r) * D3 + j];
        }
#pragma unroll
        for (int i = 0; i < 4; ++i) {
            int flat = tid + i * 256;
            int r = flat >> 3, j = (flat & 7) * 8;
            union { uint4 u; __half h[8]; } vv;
            vv.u = *(const uint4*)&Vg[(long)(kv0 + r) * D3 + j];
#pragma unroll
            for (int q = 0; q < 8; ++q) Vs[j + q][r] = vv.h[q];
        }
        __syncthreads();

        // ---- S = Q K^T ----
        float acc[16][4];
#pragma unroll
        for (int j = 0; j < 16; ++j)
#pragma unroll
            for (int q = 0; q < 4; ++q) acc[j][q] = 0.f;
#pragma unroll
        for (int kt = 0; kt < 4; ++kt) {
            const int kb = kt * 16 + tg * 2;
            unsigned a0 = *(const unsigned*)&Qs[m0 + gid][kb];
            unsigned a1 = *(const unsigned*)&Qs[m0 + gid + 8][kb];
            unsigned a2 = *(const unsigned*)&Qs[m0 + gid][kb + 8];
            unsigned a3 = *(const unsigned*)&Qs[m0 + gid + 8][kb + 8];
#pragma unroll
            for (int j = 0; j < 16; ++j) {
                unsigned b0 = *(const unsigned*)&Ks[j * 8 + gid][kb];
                unsigned b1 = *(const unsigned*)&Ks[j * 8 + gid][kb + 8];
                mma_f16(acc[j], a0, a1, a2, a3, b0, b1);
            }
        }

        // ---- + spatial bias; row max ----
        const float* sw0 = swb + (long)(bm + m0 + gid) * N_ + kv0;
        const float* sw1 = sw0 + 8 * N_;
        float mx0 = -3.4e38f, mx1 = -3.4e38f;
#pragma unroll
        for (int j = 0; j < 16; ++j) {
            float2 s0 = *(const float2*)&sw0[j * 8 + tg * 2];
            float2 s1 = *(const float2*)&sw1[j * 8 + tg * 2];
            acc[j][0] += s0.x; acc[j][1] += s0.y;
            acc[j][2] += s1.x; acc[j][3] += s1.y;
            mx0 = fmaxf(mx0, fmaxf(acc[j][0], acc[j][1]));
            mx1 = fmaxf(mx1, fmaxf(acc[j][2], acc[j][3]));
        }
#pragma unroll
        for (int o = 1; o <= 2; o <<= 1) {
            mx0 = fmaxf(mx0, __shfl_xor_sync(0xffffffffu, mx0, o));
            mx1 = fmaxf(mx1, __shfl_xor_sync(0xffffffffu, mx1, o));
        }

        const float mn0 = fmaxf(m0r, mx0), mn1 = fmaxf(m1r, mx1);
        const float sc0 = __expf(m0r - mn0), sc1 = __expf(m1r - mn1);
        m0r = mn0; m1r = mn1;

        float rs0 = 0.f, rs1 = 0.f;
        unsigned pr[16][2];
#pragma unroll
        for (int j = 0; j < 16; ++j) {
            float p0 = __expf(acc[j][0] - mn0);
            float p1 = __expf(acc[j][1] - mn0);
            float p2 = __expf(acc[j][2] - mn1);
            float p3 = __expf(acc[j][3] - mn1);
            rs0 += p0 + p1; rs1 += p2 + p3;
            pr[j][0] = pack2(p0, p1);
            pr[j][1] = pack2(p2, p3);
        }
#pragma unroll
        for (int o = 1; o <= 2; o <<= 1) {
            rs0 += __shfl_xor_sync(0xffffffffu, rs0, o);
            rs1 += __shfl_xor_sync(0xffffffffu, rs1, o);
        }
        l0 = l0 * sc0 + rs0;
        l1 = l1 * sc1 + rs1;

#pragma unroll
        for (int jo = 0; jo < 8; ++jo) {
            oacc[jo][0] *= sc0; oacc[jo][1] *= sc0;
            oacc[jo][2] *= sc1; oacc[jo][3] *= sc1;
        }
#pragma unroll
        for (int kt2 = 0; kt2 < 8; ++kt2) {
            unsigned a0 = pr[2 * kt2][0],     a1 = pr[2 * kt2][1];
            unsigned a2 = pr[2 * kt2 + 1][0], a3 = pr[2 * kt2 + 1][1];
            const int kb = kt2 * 16 + tg * 2;
#pragma unroll
            for (int jo = 0; jo < 8; ++jo) {
                unsigned b0 = *(const unsigned*)&Vs[jo * 8 + gid][kb];
                unsigned b1 = *(const unsigned*)&Vs[jo * 8 + gid][kb + 8];
                mma_f16(oacc[jo], a0, a1, a2, a3, b0, b1);
            }
        }
    }

    const float i0 = 1.f / l0, i1 = 1.f / l1;
    __half* o0 = outp + (long)(b * N_ + bm + m0 + gid) * D_ + h * DH_;
    __half* o1 = o0 + 8 * D_;
#pragma unroll
    for (int jo = 0; jo < 8; ++jo) {
        *(unsigned*)&o0[jo * 8 + tg * 2] = pack2(oacc[jo][0] * i0, oacc[jo][1] * i0);
        *(unsigned*)&o1[jo * 8 + tg * 2] = pack2(oacc[jo][2] * i1, oacc[jo][3] * i1);
    }
}

// ---------------- fp16 GEMM, cp.async double-buffered -------------------------
// C[M,N] = A[M,K](half,row) @ B[N,K](half,row)^T
// FLAGS: 1=bias 2=gelu 4=resid(fp32) 8=half-out 16=scale cols<768 by 1/8
template<int FLAGS>
__global__ void __launch_bounds__(256, 2)
gemm_h2(const __half* __restrict__ A, const __half* __restrict__ B,
        void* __restrict__ Cv, int K, int lda, int ldc,
        const float* __restrict__ bias,
        const float* __restrict__ resid, int ldres) {
    constexpr int SK = 40;
    __shared__ __half As[2][128][SK];
    __shared__ __half Bs[2][128][SK];

    const int tid  = threadIdx.x;
    const int lane = tid & 31;
    const int gid  = lane >> 2;
    const int tg   = lane & 3;
    const int warp = tid >> 5;
    const int mwarp = (warp >> 2) * 64;
    const int nwarp = (warp & 3) * 32;

    const int bn = blockIdx.x * 128;
    const int bm = blockIdx.y * 128;
    const int lr = tid >> 2, lj = (tid & 3) * 8;   // loader row/chunk

    const __half* Ap0 = A + (long)(bm + lr) * lda + lj;
    const __half* Ap1 = A + (long)(bm + 64 + lr) * lda + lj;
    const __half* Bp0 = B + (long)(bn + lr) * K + lj;
    const __half* Bp1 = B + (long)(bn + 64 + lr) * K + lj;
    const uint32_t sa0 = smem_u32(&As[0][lr][lj]),      sa1 = smem_u32(&As[0][64 + lr][lj]);
    const uint32_t sb0 = smem_u32(&Bs[0][lr][lj]),      sb1 = smem_u32(&Bs[0][64 + lr][lj]);
    const uint32_t bufst = 128 * SK * 2;   // bytes per buffer

    float acc[4][4][4] = {};
    const int T = K >> 5;

    auto load = [&](int t, int buf) {
        const uint32_t o = buf * bufst;
        const long ko = (long)t * 32;
        asm volatile("cp.async.cg.shared.global [%0],[%1],16;" :: "r"(sa0 + o), "l"(Ap0 + ko) : "memory");
        asm volatile("cp.async.cg.shared.global [%0],[%1],16;" :: "r"(sa1 + o), "l"(Ap1 + ko) : "memory");
        asm volatile("cp.async.cg.shared.global [%0],[%1],16;" :: "r"(sb0 + o), "l"(Bp0 + ko) : "memory");
        asm volatile("cp.async.cg.shared.global [%0],[%1],16;" :: "r"(sb1 + o), "l"(Bp1 + ko) : "memory");
        asm volatile("cp.async.commit_group;" ::: "memory");
    };

    load(0, 0);
    for (int t = 0; t < T; ++t) {
        const int buf = t & 1;
        asm volatile("cp.async.wait_group 0;" ::: "memory");
        __syncthreads();
        if (t + 1 < T) load(t + 1, (t + 1) & 1);

        const __half (*Af)[SK] = As[buf];
        const __half (*Bf)[SK] = Bs[buf];
#pragma unroll
        for (int ks = 0; ks < 2; ++ks) {
            const int kb = ks * 16 + tg * 2;
            unsigned af[4][4], bf[4][2];
#pragma unroll
            for (int i = 0; i < 4; ++i) {
                int mm = mwarp + i * 16 + gid;
                af[i][0] = *(const unsigned*)&Af[mm][kb];
                af[i][1] = *(const unsigned*)&Af[mm + 8][kb];
                af[i][2] = *(const unsigned*)&Af[mm][kb + 8];
                af[i][3] = *(const unsigned*)&Af[mm + 8][kb + 8];
            }
#pragma unroll
            for (int j = 0; j < 4; ++j) {
                int n = nwarp + j * 8 + gid;
                bf[j][0] = *(const unsigned*)&Bf[n][kb];
                bf[j][1] = *(const unsigned*)&Bf[n][kb + 8];
            }
#pragma unroll
            for (int i = 0; i < 4; ++i)
#pragma unroll
                for (int j = 0; j < 4; ++j)
                    mma_f16(acc[i][j], af[i][0], af[i][1], af[i][2], af[i][3],
                            bf[j][0], bf[j][1]);
        }
        __syncthreads();
    }

    // ---- epilogue ----
#pragma unroll
    for (int i = 0; i < 4; ++i) {
        const int r0 = bm + mwarp + i * 16 + gid;
#pragma unroll
        for (int j = 0; j < 4; ++j) {
            const int c = bn + nwarp + j * 8 + tg * 2;
#pragma unroll
            for (int hh = 0; hh < 2; ++hh) {
                const int row = r0 + hh * 8;
                float2 p = make_float2(acc[i][j][hh * 2], acc[i][j][hh * 2 + 1]);
                if (FLAGS & 16) { const float sc = (c < D_) ? 0.125f : 1.f; p.x *= sc; p.y *= sc; }
                if (FLAGS & 1)  { p.x += bias[c]; p.y += bias[c + 1]; }
                if (FLAGS & 2)  {
                    p.x = 0.5f * p.x * (1.f + erff(p.x * 0.70710678118654752f));
                    p.y = 0.5f * p.y * (1.f + erff(p.y * 0.70710678118654752f));
                }
                if (FLAGS & 4)  {
                    float2 r = *(const float2*)&resid[(long)row * ldres + c];
                    p.x += r.x; p.y += r.y;
                }
                if (FLAGS & 8)
                    *(unsigned*)&((__half*)Cv)[(long)row * ldc + c] = pack2(p.x, p.y);
                else
                    *(float2*)&((float*)Cv)[(long)row * ldc + c] = p;
            }
        }
    }
}

// ---------------- launch ------------------------------------------------------
extern "C" void kernel_launch(void* const* d_in, const int* in_sizes, int n_in,
                              void* d_out, int out_size) {
    const float* x_in  = (const float*)d_in[0];
    const float* sw    = (const float*)d_in[1];
    const float* ln1g  = (const float*)d_in[2];
    const float* ln1b  = (const float*)d_in[3];
    const float* wqkv  = (const float*)d_in[4];
    const float* wout  = (const float*)d_in[5];
    const float* bout  = (const float*)d_in[6];
    const float* ln2g  = (const float*)d_in[7];
    const float* ln2b  = (const float*)d_in[8];
    const float* w1    = (const float*)d_in[9];
    const float* b1    = (const float*)d_in[10];
    const float* w2    = (const float*)d_in[11];
    const float* b2    = (const float*)d_in[12];
    float* out = (float*)d_out;

    float *px;
    __half *pxn, *pqkv, *patt, *ph, *pwT;
    cudaGetSymbolAddress((void**)&px,   g_x);
    cudaGetSymbolAddress((void**)&pxn,  g_xnh);
    cudaGetSymbolAddress((void**)&pqkv, g_qkvh);
    cudaGetSymbolAddress((void**)&patt, g_atth);
    cudaGetSymbolAddress((void**)&ph,   g_hh);
    cudaGetSymbolAddress((void**)&pwT,  g_whT);

    cudaFuncSetAttribute(flash_k, cudaFuncAttributeMaxDynamicSharedMemorySize, FL_SMEM);

    // one-time weight transpose+cvt (runs per replay; ~40us)
    for (int l = 0; l < L_; ++l) {
        __half* wl = pwT + (size_t)l * WT_LSTR;
        tr_h<<<dim3(D3/32, D_/32),  dim3(32,8)>>>(wqkv + (long)l*D_*D3,  wl + OFF_QKVT, D_, D3);
        tr_h<<<dim3(D_/32, D_/32),  dim3(32,8)>>>(wout + (long)l*D_*D_,  wl + OFF_OWT,  D_, D_);
        tr_h<<<dim3(DFF/32, D_/32), dim3(32,8)>>>(w1   + (long)l*D_*DFF, wl + OFF_W1T,  D_, DFF);
        tr_h<<<dim3(D_/32, DFF/32), dim3(32,8)>>>(w2   + (long)l*DFF*D_, wl + OFF_W2T,  DFF, D_);
    }

    for (int l = 0; l < L_; ++l) {
        const float* xcur = (l == 0) ? x_in : px;
        __half* wl = pwT + (size_t)l * WT_LSTR;

        // LN1 -> fp16 xn
        ln_kernel<<<ROWS, 256>>>(xcur, ln1g + (long)l * D_, ln1b + (long)l * D_, pxn);

        // QKV -> fp16 qkv (Q cols pre-scaled by 1/8)
        gemm_h2<8|16><<<dim3(D3/128, ROWS/128), 256>>>(
            pxn, wl + OFF_QKVT, pqkv, D_, D_, D3, nullptr, nullptr, 0);

        // fused attention -> fp16 attn
        flash_k<<<dim3(N_/128, ZHB), 256, FL_SMEM>>>(pqkv, sw, patt);

        // proj + bias + residual -> fp32 x
        gemm_h2<1|4><<<dim3(D_/128, ROWS/128), 256>>>(
            patt, wl + OFF_OWT, px, D_, D_, D_,
            bout + (long)l * D_, xcur, D_);

        // LN2 -> fp16 xn
        ln_kernel<<<ROWS, 256>>>(px, ln2g + (long)l * D_, ln2b + (long)l * D_, pxn);

        // FC1 + bias + GELU -> fp16 h
        gemm_h2<1|2|8><<<dim3(DFF/128, ROWS/128), 256>>>(
            pxn, wl + OFF_W1T, ph, D_, D_, DFF,
            b1 + (long)l * DFF, nullptr, 0);

        // FC2 + bias + residual -> fp32 (last layer -> d_out)
        float* cdst = (l == L_ - 1) ? out : px;
        gemm_h2<1|4><<<dim3(D_/128, ROWS/128), 256>>>(
            ph, wl + OFF_W2T, cdst, DFF, DFF, D_,
            b2 + (long)l * D_, px, D_);
    }
}

// round 10
// speedup vs baseline: 6.0460x; 1.1006x over previous
#include <cuda_runtime.h>
#include <cuda_fp16.h>
#include <math.h>
#include <stdint.h>

#define D_   768
#define H_   12
#define L_   6
#define B_   4
#define N_   1024
#define DH_  64
#define ROWS (B_*N_)      /* 4096 */
#define D3   (3*D_)       /* 2304 */
#define DFF  (4*D_)       /* 3072 */
#define ZHB  (B_*H_)      /* 48   */

// transposed fp16 weight offsets (halfs, per layer)
#define OFF_QKVT 0
#define OFF_OWT  (768*2304)
#define OFF_W1T  (OFF_OWT + 768*768)
#define OFF_W2T  (OFF_W1T + 768*3072)
#define WT_LSTR  (OFF_W2T + 3072*768)   /* 7077888 */

// ---------------- scratch ----------------------------------------------------
__device__ float  g_x   [ROWS*(size_t)D_];
__device__ __half g_xnh [ROWS*(size_t)D_];
__device__ __half g_qkvh[ROWS*(size_t)D3];
__device__ __half g_atth[ROWS*(size_t)D_];
__device__ __half g_hh  [ROWS*(size_t)DFF];
__device__ __half g_whT [(size_t)L_*WT_LSTR];

__device__ __forceinline__ unsigned pack2(float x, float y) {
    __half2 h = __floats2half2_rn(x, y);
    return *reinterpret_cast<unsigned*>(&h);
}
__device__ __forceinline__ void mma_f16(float* c,
                                        unsigned a0, unsigned a1, unsigned a2, unsigned a3,
                                        unsigned b0, unsigned b1) {
    asm volatile(
        "mma.sync.aligned.m16n8k16.row.col.f32.f16.f16.f32 "
        "{%0,%1,%2,%3}, {%4,%5,%6,%7}, {%8,%9}, {%0,%1,%2,%3};"
        : "+f"(c[0]), "+f"(c[1]), "+f"(c[2]), "+f"(c[3])
        : "r"(a0), "r"(a1), "r"(a2), "r"(a3), "r"(b0), "r"(b1));
}
__device__ __forceinline__ uint32_t smem_u32(const void* p) {
    uint32_t a;
    asm("{ .reg .u64 t; cvta.to.shared.u64 t, %1; cvt.u32.u64 %0, t; }" : "=r"(a) : "l"(p));
    return a;
}

// ---------------- batched weight transpose+cvt (z = layer) --------------------
__global__ void tr_hL(const float* __restrict__ src, __half* __restrict__ dst,
                      int R, int C, long srcStr, long dstStr) {
    __shared__ float t[32][33];
    const float* s = src + (long)blockIdx.z * srcStr;
    __half*      d = dst + (long)blockIdx.z * dstStr;
    const int c0 = blockIdx.x * 32, r0 = blockIdx.y * 32;
    const int x = threadIdx.x, y = threadIdx.y;
#pragma unroll
    for (int i = 0; i < 32; i += 8)
        t[y + i][x] = s[(long)(r0 + y + i) * C + c0 + x];
    __syncthreads();
#pragma unroll
    for (int i = 0; i < 32; i += 8)
        d[(long)(c0 + y + i) * R + r0 + x] = __float2half(t[x][y + i]);
}

// ---------------- LayerNorm (fp32 in, fp16 out) --------------------------------
__global__ void ln_kernel(const float* __restrict__ x,
                          const float* __restrict__ g,
                          const float* __restrict__ b,
                          __half* __restrict__ y) {
    const int row = blockIdx.x;
    const float* xr = x + (size_t)row * D_;
    __half*      yr = y + (size_t)row * D_;
    const int tid = threadIdx.x;

    float v[3], s = 0.f, s2 = 0.f;
#pragma unroll
    for (int i = 0; i < 3; ++i) {
        float t = xr[tid + i * 256];
        v[i] = t; s += t; s2 += t * t;
    }
#pragma unroll
    for (int o = 16; o; o >>= 1) {
        s  += __shfl_xor_sync(0xffffffffu, s,  o);
        s2 += __shfl_xor_sync(0xffffffffu, s2, o);
    }
    __shared__ float shs[8], shs2[8];
    const int w = tid >> 5;
    if ((tid & 31) == 0) { shs[w] = s; shs2[w] = s2; }
    __syncthreads();
    s = 0.f; s2 = 0.f;
#pragma unroll
    for (int i = 0; i < 8; ++i) { s += shs[i]; s2 += shs2[i]; }
    const float mean = s * (1.f / D_);
    const float var  = s2 * (1.f / D_) - mean * mean;
    const float rstd = rsqrtf(var + 1e-5f);
#pragma unroll
    for (int i = 0; i < 3; ++i) {
        int c = tid + i * 256;
        yr[c] = __float2half((v[i] - mean) * rstd * g[c] + b[c]);
    }
}

// ---------------- fused flash attention (fp16 qkv in, fp16 out) ---------------
#define FL_SMEM (2*128*72*2 + 64*136*2)
__global__ void __launch_bounds__(256)
flash_k(const __half* __restrict__ qkv, const float* __restrict__ sw,
        __half* __restrict__ outp) {
    extern __shared__ __half sm[];
    __half (*Qs)[72]  = (__half(*)[72])  sm;
    __half (*Ks)[72]  = (__half(*)[72])  (sm + 128 * 72);
    __half (*Vs)[136] = (__half(*)[136]) (sm + 2 * 128 * 72);

    const int tid = threadIdx.x, lane = tid & 31;
    const int gid = lane >> 2, tg = lane & 3;
    const int warp = tid >> 5;
    const int m0 = warp * 16;
    const int bm = blockIdx.x * 128;
    const int z = blockIdx.y, b = z / H_, h = z - b * H_;

    const __half* Qg = qkv + ((long)(b * N_ + bm)) * D3 + h * DH_;
    const __half* Kg = qkv + (long)b * N_ * D3 + D_ + h * DH_;
    const __half* Vg = Kg + D_;
    const float* swb = sw + (long)b * N_ * N_;

#pragma unroll
    for (int i = 0; i < 4; ++i) {
        int flat = tid + i * 256;
        int r = flat >> 3, j = (flat & 7) * 8;
        *(uint4*)&Qs[r][j] = *(const uint4*)&Qg[(long)r * D3 + j];
    }

    float m0r = -3.4e38f, m1r = -3.4e38f, l0 = 0.f, l1 = 0.f;
    float oacc[8][4];
#pragma unroll
    for (int jo = 0; jo < 8; ++jo)
#pragma unroll
        for (int q = 0; q < 4; ++q) oacc[jo][q] = 0.f;

    for (int kv0 = 0; kv0 < N_; kv0 += 128) {
        __syncthreads();
#pragma unroll
        for (int i = 0; i < 4; ++i) {
            int flat = tid + i * 256;
            int r = flat >> 3, j = (flat & 7) * 8;
            *(uint4*)&Ks[r][j] = *(const uint4*)&Kg[(long)(kv0 + r) * D3 + j];
        }
#pragma unroll
        for (int i = 0; i < 4; ++i) {
            int flat = tid + i * 256;
            int r = flat >> 3, j = (flat & 7) * 8;
            union { uint4 u; __half h[8]; } vv;
            vv.u = *(const uint4*)&Vg[(long)(kv0 + r) * D3 + j];
#pragma unroll
            for (int q = 0; q < 8; ++q) Vs[j + q][r] = vv.h[q];
        }
        __syncthreads();

        float acc[16][4];
#pragma unroll
        for (int j = 0; j < 16; ++j)
#pragma unroll
            for (int q = 0; q < 4; ++q) acc[j][q] = 0.f;
#pragma unroll
        for (int kt = 0; kt < 4; ++kt) {
            const int kb = kt * 16 + tg * 2;
            unsigned a0 = *(const unsigned*)&Qs[m0 + gid][kb];
            unsigned a1 = *(const unsigned*)&Qs[m0 + gid + 8][kb];
            unsigned a2 = *(const unsigned*)&Qs[m0 + gid][kb + 8];
            unsigned a3 = *(const unsigned*)&Qs[m0 + gid + 8][kb + 8];
#pragma unroll
            for (int j = 0; j < 16; ++j) {
                unsigned b0 = *(const unsigned*)&Ks[j * 8 + gid][kb];
                unsigned b1 = *(const unsigned*)&Ks[j * 8 + gid][kb + 8];
                mma_f16(acc[j], a0, a1, a2, a3, b0, b1);
            }
        }

        const float* sw0 = swb + (long)(bm + m0 + gid) * N_ + kv0;
        const float* sw1 = sw0 + 8 * N_;
        float mx0 = -3.4e38f, mx1 = -3.4e38f;
#pragma unroll
        for (int j = 0; j < 16; ++j) {
            float2 s0 = *(const float2*)&sw0[j * 8 + tg * 2];
            float2 s1 = *(const float2*)&sw1[j * 8 + tg * 2];
            acc[j][0] += s0.x; acc[j][1] += s0.y;
            acc[j][2] += s1.x; acc[j][3] += s1.y;
            mx0 = fmaxf(mx0, fmaxf(acc[j][0], acc[j][1]));
            mx1 = fmaxf(mx1, fmaxf(acc[j][2], acc[j][3]));
        }
#pragma unroll
        for (int o = 1; o <= 2; o <<= 1) {
            mx0 = fmaxf(mx0, __shfl_xor_sync(0xffffffffu, mx0, o));
            mx1 = fmaxf(mx1, __shfl_xor_sync(0xffffffffu, mx1, o));
        }

        const float mn0 = fmaxf(m0r, mx0), mn1 = fmaxf(m1r, mx1);
        const float sc0 = __expf(m0r - mn0), sc1 = __expf(m1r - mn1);
        m0r = mn0; m1r = mn1;

        float rs0 = 0.f, rs1 = 0.f;
        unsigned pr[16][2];
#pragma unroll
        for (int j = 0; j < 16; ++j) {
            float p0 = __expf(acc[j][0] - mn0);
            float p1 = __expf(acc[j][1] - mn0);
            float p2 = __expf(acc[j][2] - mn1);
            float p3 = __expf(acc[j][3] - mn1);
            rs0 += p0 + p1; rs1 += p2 + p3;
            pr[j][0] = pack2(p0, p1);
            pr[j][1] = pack2(p2, p3);
        }
#pragma unroll
        for (int o = 1; o <= 2; o <<= 1) {
            rs0 += __shfl_xor_sync(0xffffffffu, rs0, o);
            rs1 += __shfl_xor_sync(0xffffffffu, rs1, o);
        }
        l0 = l0 * sc0 + rs0;
        l1 = l1 * sc1 + rs1;

#pragma unroll
        for (int jo = 0; jo < 8; ++jo) {
            oacc[jo][0] *= sc0; oacc[jo][1] *= sc0;
            oacc[jo][2] *= sc1; oacc[jo][3] *= sc1;
        }
#pragma unroll
        for (int kt2 = 0; kt2 < 8; ++kt2) {
            unsigned a0 = pr[2 * kt2][0],     a1 = pr[2 * kt2][1];
            unsigned a2 = pr[2 * kt2 + 1][0], a3 = pr[2 * kt2 + 1][1];
            const int kb = kt2 * 16 + tg * 2;
#pragma unroll
            for (int jo = 0; jo < 8; ++jo) {
                unsigned b0 = *(const unsigned*)&Vs[jo * 8 + gid][kb];
                unsigned b1 = *(const unsigned*)&Vs[jo * 8 + gid][kb + 8];
                mma_f16(oacc[jo], a0, a1, a2, a3, b0, b1);
            }
        }
    }

    const float i0 = 1.f / l0, i1 = 1.f / l1;
    __half* o0 = outp + (long)(b * N_ + bm + m0 + gid) * D_ + h * DH_;
    __half* o1 = o0 + 8 * D_;
#pragma unroll
    for (int jo = 0; jo < 8; ++jo) {
        *(unsigned*)&o0[jo * 8 + tg * 2] = pack2(oacc[jo][0] * i0, oacc[jo][1] * i0);
        *(unsigned*)&o1[jo * 8 + tg * 2] = pack2(oacc[jo][2] * i1, oacc[jo][3] * i1);
    }
}

// ---------------- fp16 GEMM, BK=64, 2-stage cp.async --------------------------
// C[M,N] = A[M,K](half,row) @ B[N,K](half,row)^T
// FLAGS: 1=bias 2=gelu 4=resid(fp32) 8=half-out 16=scale cols<768 by 1/8
#define G3_SK    72                       /* smem halfs per row */
#define G3_ATILE (128*G3_SK)              /* 9216 halfs */
#define G3_STAGE (2*G3_ATILE)             /* A+B per stage, halfs */
#define G3_SMEM  (2*G3_STAGE*2)           /* bytes: 73728 */
template<int FLAGS>
__global__ void __launch_bounds__(256, 2)
gemm_h3(const __half* __restrict__ A, const __half* __restrict__ B,
        void* __restrict__ Cv, int K, int lda, int ldc,
        const float* __restrict__ bias,
        const float* __restrict__ resid, int ldres) {
    extern __shared__ __half sm3[];
    const int tid  = threadIdx.x;
    const int lane = tid & 31;
    const int gid  = lane >> 2;
    const int tg   = lane & 3;
    const int warp = tid >> 5;
    const int mwarp = (warp >> 2) * 64;
    const int nwarp = (warp & 3) * 32;
    const int bn = blockIdx.x * 128;
    const int bm = blockIdx.y * 128;

    const int lr = tid >> 3;             // 0..31
    const int lj = (tid & 7) * 8;        // 0..56 halfs (16B chunks)
    const uint32_t smb = smem_u32(sm3);
    const __half* Apt = A + (long)(bm + lr) * lda + lj;
    const __half* Bpt = B + (long)(bn + lr) * K + lj;

    float acc[4][4][4] = {};
    const int T = K >> 6;

    auto load = [&](int t, int s) {
        const uint32_t oA = smb + s * (G3_STAGE * 2) + (lr * G3_SK + lj) * 2;
        const uint32_t oB = oA + G3_ATILE * 2;
        const long ko = (long)t * 64;
#pragma unroll
        for (int i = 0; i < 4; ++i) {
            asm volatile("cp.async.cg.shared.global [%0],[%1],16;"
                :: "r"(oA + i * 32 * G3_SK * 2), "l"(Apt + ko + (long)i * 32 * lda) : "memory");
            asm volatile("cp.async.cg.shared.global [%0],[%1],16;"
                :: "r"(oB + i * 32 * G3_SK * 2), "l"(Bpt + ko + (long)i * 32 * K) : "memory");
        }
        asm volatile("cp.async.commit_group;" ::: "memory");
    };

    load(0, 0);
    for (int t = 0; t < T; ++t) {
        const int s = t & 1;
        if (t + 1 < T) {
            load(t + 1, s ^ 1);
            asm volatile("cp.async.wait_group 1;" ::: "memory");
        } else {
            asm volatile("cp.async.wait_group 0;" ::: "memory");
        }
        __syncthreads();

        const __half (*Af)[G3_SK] = (const __half(*)[G3_SK])(sm3 + s * G3_STAGE);
        const __half (*Bf)[G3_SK] = (const __half(*)[G3_SK])(sm3 + s * G3_STAGE + G3_ATILE);
#pragma unroll
        for (int ks = 0; ks < 4; ++ks) {
            const int kb = ks * 16 + tg * 2;
            unsigned af[4][4], bf[4][2];
#pragma unroll
            for (int i = 0; i < 4; ++i) {
                int mm = mwarp + i * 16 + gid;
                af[i][0] = *(const unsigned*)&Af[mm][kb];
                af[i][1] = *(const unsigned*)&Af[mm + 8][kb];
                af[i][2] = *(const unsigned*)&Af[mm][kb + 8];
                af[i][3] = *(const unsigned*)&Af[mm + 8][kb + 8];
            }
#pragma unroll
            for (int j = 0; j < 4; ++j) {
                int n = nwarp + j * 8 + gid;
                bf[j][0] = *(const unsigned*)&Bf[n][kb];
                bf[j][1] = *(const unsigned*)&Bf[n][kb + 8];
            }
#pragma unroll
            for (int i = 0; i < 4; ++i)
#pragma unroll
                for (int j = 0; j < 4; ++j)
                    mma_f16(acc[i][j], af[i][0], af[i][1], af[i][2], af[i][3],
                            bf[j][0], bf[j][1]);
        }
        __syncthreads();
    }

    // ---- epilogue ----
#pragma unroll
    for (int i = 0; i < 4; ++i) {
        const int r0 = bm + mwarp + i * 16 + gid;
#pragma unroll
        for (int j = 0; j < 4; ++j) {
            const int c = bn + nwarp + j * 8 + tg * 2;
#pragma unroll
            for (int hh = 0; hh < 2; ++hh) {
                const int row = r0 + hh * 8;
                float2 p = make_float2(acc[i][j][hh * 2], acc[i][j][hh * 2 + 1]);
                if (FLAGS & 16) { const float sc = (c < D_) ? 0.125f : 1.f; p.x *= sc; p.y *= sc; }
                if (FLAGS & 1)  { p.x += bias[c]; p.y += bias[c + 1]; }
                if (FLAGS & 2)  {
                    p.x = 0.5f * p.x * (1.f + erff(p.x * 0.70710678118654752f));
                    p.y = 0.5f * p.y * (1.f + erff(p.y * 0.70710678118654752f));
                }
                if (FLAGS & 4)  {
                    float2 r = *(const float2*)&resid[(long)row * ldres + c];
                    p.x += r.x; p.y += r.y;
                }
                if (FLAGS & 8)
                    *(unsigned*)&((__half*)Cv)[(long)row * ldc + c] = pack2(p.x, p.y);
                else
                    *(float2*)&((float*)Cv)[(long)row * ldc + c] = p;
            }
        }
    }
}

// ---------------- launch ------------------------------------------------------
extern "C" void kernel_launch(void* const* d_in, const int* in_sizes, int n_in,
                              void* d_out, int out_size) {
    const float* x_in  = (const float*)d_in[0];
    const float* sw    = (const float*)d_in[1];
    const float* ln1g  = (const float*)d_in[2];
    const float* ln1b  = (const float*)d_in[3];
    const float* wqkv  = (const float*)d_in[4];
    const float* wout  = (const float*)d_in[5];
    const float* bout  = (const float*)d_in[6];
    const float* ln2g  = (const float*)d_in[7];
    const float* ln2b  = (const float*)d_in[8];
    const float* w1    = (const float*)d_in[9];
    const float* b1    = (const float*)d_in[10];
    const float* w2    = (const float*)d_in[11];
    const float* b2    = (const float*)d_in[12];
    float* out = (float*)d_out;

    float *px;
    __half *pxn, *pqkv, *patt, *ph, *pwT;
    cudaGetSymbolAddress((void**)&px,   g_x);
    cudaGetSymbolAddress((void**)&pxn,  g_xnh);
    cudaGetSymbolAddress((void**)&pqkv, g_qkvh);
    cudaGetSymbolAddress((void**)&patt, g_atth);
    cudaGetSymbolAddress((void**)&ph,   g_hh);
    cudaGetSymbolAddress((void**)&pwT,  g_whT);

    cudaFuncSetAttribute(flash_k, cudaFuncAttributeMaxDynamicSharedMemorySize, FL_SMEM);
    cudaFuncSetAttribute(gemm_h3<8|16>,  cudaFuncAttributeMaxDynamicSharedMemorySize, G3_SMEM);
    cudaFuncSetAttribute(gemm_h3<1|4>,   cudaFuncAttributeMaxDynamicSharedMemorySize, G3_SMEM);
    cudaFuncSetAttribute(gemm_h3<1|2|8>, cudaFuncAttributeMaxDynamicSharedMemorySize, G3_SMEM);

    // batched weight transpose+cvt (4 launches, z = layer)
    tr_hL<<<dim3(D3/32, D_/32, L_),  dim3(32,8)>>>(wqkv, pwT + OFF_QKVT, D_, D3,
                                                   (long)D_*D3,  (long)WT_LSTR);
    tr_hL<<<dim3(D_/32, D_/32, L_),  dim3(32,8)>>>(wout, pwT + OFF_OWT,  D_, D_,
                                                   (long)D_*D_,  (long)WT_LSTR);
    tr_hL<<<dim3(DFF/32, D_/32, L_), dim3(32,8)>>>(w1,   pwT + OFF_W1T,  D_, DFF,
                                                   (long)D_*DFF, (long)WT_LSTR);
    tr_hL<<<dim3(D_/32, DFF/32, L_), dim3(32,8)>>>(w2,   pwT + OFF_W2T,  DFF, D_,
                                                   (long)DFF*D_, (long)WT_LSTR);

    for (int l = 0; l < L_; ++l) {
        const float* xcur = (l == 0) ? x_in : px;
        __half* wl = pwT + (size_t)l * WT_LSTR;

        // LN1 -> fp16 xn
        ln_kernel<<<ROWS, 256>>>(xcur, ln1g + (long)l * D_, ln1b + (long)l * D_, pxn);

        // QKV -> fp16 qkv (Q cols pre-scaled by 1/8)
        gemm_h3<8|16><<<dim3(D3/128, ROWS/128), 256, G3_SMEM>>>(
            pxn, wl + OFF_QKVT, pqkv, D_, D_, D3, nullptr, nullptr, 0);

        // fused attention -> fp16 attn
        flash_k<<<dim3(N_/128, ZHB), 256, FL_SMEM>>>(pqkv, sw, patt);

        // proj + bias + residual -> fp32 x
        gemm_h3<1|4><<<dim3(D_/128, ROWS/128), 256, G3_SMEM>>>(
            patt, wl + OFF_OWT, px, D_, D_, D_,
            bout + (long)l * D_, xcur, D_);

        // LN2 -> fp16 xn
        ln_kernel<<<ROWS, 256>>>(px, ln2g + (long)l * D_, ln2b + (long)l * D_, pxn);

        // FC1 + bias + GELU -> fp16 h
        gemm_h3<1|2|8><<<dim3(DFF/128, ROWS/128), 256, G3_SMEM>>>(
            pxn, wl + OFF_W1T, ph, D_, D_, DFF,
            b1 + (long)l * DFF, nullptr, 0);

        // FC2 + bias + residual -> fp32 (last layer -> d_out)
        float* cdst = (l == L_ - 1) ? out : px;
        gemm_h3<1|4><<<dim3(D_/128, ROWS/128), 256, G3_SMEM>>>(
            ph, wl + OFF_W2T, cdst, DFF, DFF, D_,
            b2 + (long)l * D_, px, D_);
    }
}

// round 11
// speedup vs baseline: 6.1420x; 1.0159x over previous
#include <cuda_runtime.h>
#include <cuda_fp16.h>
#include <math.h>
#include <stdint.h>

#define D_   768
#define H_   12
#define L_   6
#define B_   4
#define N_   1024
#define DH_  64
#define ROWS (B_*N_)      /* 4096 */
#define D3   (3*D_)       /* 2304 */
#define DFF  (4*D_)       /* 3072 */
#define ZHB  (B_*H_)      /* 48   */

#define OFF_QKVT 0
#define OFF_OWT  (768*2304)
#define OFF_W1T  (OFF_OWT + 768*768)
#define OFF_W2T  (OFF_W1T + 768*3072)
#define WT_LSTR  (OFF_W2T + 3072*768)

// ---------------- scratch ----------------------------------------------------
__device__ float  g_x   [ROWS*(size_t)D_];
__device__ __half g_xnh [ROWS*(size_t)D_];
__device__ __half g_qkvh[ROWS*(size_t)D3];
__device__ __half g_atth[ROWS*(size_t)D_];
__device__ __half g_hh  [ROWS*(size_t)DFF];
__device__ __half g_whT [(size_t)L_*WT_LSTR];

__device__ __forceinline__ unsigned pack2(float x, float y) {
    __half2 h = __floats2half2_rn(x, y);
    return *reinterpret_cast<unsigned*>(&h);
}
__device__ __forceinline__ void mma_f16(float* c,
                                        unsigned a0, unsigned a1, unsigned a2, unsigned a3,
                                        unsigned b0, unsigned b1) {
    asm volatile(
        "mma.sync.aligned.m16n8k16.row.col.f32.f16.f16.f32 "
        "{%0,%1,%2,%3}, {%4,%5,%6,%7}, {%8,%9}, {%0,%1,%2,%3};"
        : "+f"(c[0]), "+f"(c[1]), "+f"(c[2]), "+f"(c[3])
        : "r"(a0), "r"(a1), "r"(a2), "r"(a3), "r"(b0), "r"(b1));
}
__device__ __forceinline__ uint32_t smem_u32(const void* p) {
    uint32_t a;
    asm("{ .reg .u64 t; cvta.to.shared.u64 t, %1; cvt.u32.u64 %0, t; }" : "=r"(a) : "l"(p));
    return a;
}
__device__ __forceinline__ void ldm_x4(unsigned& r0, unsigned& r1, unsigned& r2, unsigned& r3,
                                       uint32_t a) {
    asm volatile("ldmatrix.sync.aligned.m8n8.x4.shared.b16 {%0,%1,%2,%3}, [%4];"
        : "=r"(r0), "=r"(r1), "=r"(r2), "=r"(r3) : "r"(a));
}
__device__ __forceinline__ void ldm_x4t(unsigned& r0, unsigned& r1, unsigned& r2, unsigned& r3,
                                        uint32_t a) {
    asm volatile("ldmatrix.sync.aligned.m8n8.x4.trans.shared.b16 {%0,%1,%2,%3}, [%4];"
        : "=r"(r0), "=r"(r1), "=r"(r2), "=r"(r3) : "r"(a));
}

// ---------------- batched weight transpose+cvt (z = layer) --------------------
__global__ void tr_hL(const float* __restrict__ src, __half* __restrict__ dst,
                      int R, int C, long srcStr, long dstStr) {
    __shared__ float t[32][33];
    const float* s = src + (long)blockIdx.z * srcStr;
    __half*      d = dst + (long)blockIdx.z * dstStr;
    const int c0 = blockIdx.x * 32, r0 = blockIdx.y * 32;
    const int x = threadIdx.x, y = threadIdx.y;
#pragma unroll
    for (int i = 0; i < 32; i += 8)
        t[y + i][x] = s[(long)(r0 + y + i) * C + c0 + x];
    __syncthreads();
#pragma unroll
    for (int i = 0; i < 32; i += 8)
        d[(long)(c0 + y + i) * R + r0 + x] = __float2half(t[x][y + i]);
}

// ---------------- LayerNorm (fp32 in, fp16 out) --------------------------------
__global__ void ln_kernel(const float* __restrict__ x,
                          const float* __restrict__ g,
                          const float* __restrict__ b,
                          __half* __restrict__ y) {
    const int row = blockIdx.x;
    const float* xr = x + (size_t)row * D_;
    __half*      yr = y + (size_t)row * D_;
    const int tid = threadIdx.x;

    float v[3], s = 0.f, s2 = 0.f;
#pragma unroll
    for (int i = 0; i < 3; ++i) {
        float t = xr[tid + i * 256];
        v[i] = t; s += t; s2 += t * t;
    }
#pragma unroll
    for (int o = 16; o; o >>= 1) {
        s  += __shfl_xor_sync(0xffffffffu, s,  o);
        s2 += __shfl_xor_sync(0xffffffffu, s2, o);
    }
    __shared__ float shs[8], shs2[8];
    const int w = tid >> 5;
    if ((tid & 31) == 0) { shs[w] = s; shs2[w] = s2; }
    __syncthreads();
    s = 0.f; s2 = 0.f;
#pragma unroll
    for (int i = 0; i < 8; ++i) { s += shs[i]; s2 += shs2[i]; }
    const float mean = s * (1.f / D_);
    const float var  = s2 * (1.f / D_) - mean * mean;
    const float rstd = rsqrtf(var + 1e-5f);
#pragma unroll
    for (int i = 0; i < 3; ++i) {
        int c = tid + i * 256;
        yr[c] = __float2half((v[i] - mean) * rstd * g[c] + b[c]);
    }
}

// ---------------- fused flash attention (ldmatrix everywhere) -----------------
// smem: Qs[128][72], Ks[128][72], Vs[128][72] (V untransposed; trans at load)
#define FL_SMEM (3*128*72*2)
__global__ void __launch_bounds__(256)
flash_k(const __half* __restrict__ qkv, const float* __restrict__ sw,
        __half* __restrict__ outp) {
    extern __shared__ __half sm[];
    __half (*Qs)[72] = (__half(*)[72]) sm;
    __half (*Ks)[72] = (__half(*)[72]) (sm + 128 * 72);
    __half (*Vs)[72] = (__half(*)[72]) (sm + 2 * 128 * 72);

    const int tid = threadIdx.x, lane = tid & 31;
    const int gid = lane >> 2, tg = lane & 3;
    const int warp = tid >> 5;
    const int m0 = warp * 16;
    const int bm = blockIdx.x * 128;
    const int z = blockIdx.y, b = z / H_, h = z - b * H_;

    // ldmatrix lane offsets
    const int roff = (lane & 7) + ((lane >> 3) & 1) * 8;
    const int coff = ((lane >> 4) & 1) * 8;

    const __half* Qg = qkv + ((long)(b * N_ + bm)) * D3 + h * DH_;
    const __half* Kg = qkv + (long)b * N_ * D3 + D_ + h * DH_;
    const __half* Vg = Kg + D_;
    const float* swb = sw + (long)b * N_ * N_;

#pragma unroll
    for (int i = 0; i < 4; ++i) {
        int flat = tid + i * 256;
        int r = flat >> 3, j = (flat & 7) * 8;
        *(uint4*)&Qs[r][j] = *(const uint4*)&Qg[(long)r * D3 + j];
    }

    const uint32_t qb = smem_u32(sm) + (uint32_t)(((m0 + roff) * 72 + coff) * 2);
    const uint32_t kbb = smem_u32(sm) + (uint32_t)((128 * 72 + roff * 72 + coff) * 2);
    const uint32_t vbb = smem_u32(sm) + (uint32_t)((2 * 128 * 72 + roff * 72 + coff) * 2);

    float m0r = -3.4e38f, m1r = -3.4e38f, l0 = 0.f, l1 = 0.f;
    float oacc[8][4];
#pragma unroll
    for (int jo = 0; jo < 8; ++jo)
#pragma unroll
        for (int q = 0; q < 4; ++q) oacc[jo][q] = 0.f;

    for (int kv0 = 0; kv0 < N_; kv0 += 128) {
        __syncthreads();
#pragma unroll
        for (int i = 0; i < 4; ++i) {
            int flat = tid + i * 256;
            int r = flat >> 3, j = (flat & 7) * 8;
            *(uint4*)&Ks[r][j] = *(const uint4*)&Kg[(long)(kv0 + r) * D3 + j];
        }
#pragma unroll
        for (int i = 0; i < 4; ++i) {
            int flat = tid + i * 256;
            int r = flat >> 3, j = (flat & 7) * 8;
            *(uint4*)&Vs[r][j] = *(const uint4*)&Vg[(long)(kv0 + r) * D3 + j];
        }
        __syncthreads();

        // ---- S = Q K^T ----
        float acc[16][4];
#pragma unroll
        for (int j = 0; j < 16; ++j)
#pragma unroll
            for (int q = 0; q < 4; ++q) acc[j][q] = 0.f;
#pragma unroll
        for (int kt = 0; kt < 4; ++kt) {
            unsigned a0, a1, a2, a3;
            ldm_x4(a0, a1, a2, a3, qb + kt * 32);
#pragma unroll
            for (int j = 0; j < 16; j += 2) {
                unsigned r0, r1, r2, r3;   // r0=bf[j][0] r1=bf[j+1][0] r2=bf[j][1] r3=bf[j+1][1]
                ldm_x4(r0, r1, r2, r3, kbb + (uint32_t)((j * 8 * 72 + kt * 16) * 2));
                mma_f16(acc[j],     a0, a1, a2, a3, r0, r2);
                mma_f16(acc[j + 1], a0, a1, a2, a3, r1, r3);
            }
        }

        // ---- + spatial bias; row max ----
        const float* sw0 = swb + (long)(bm + m0 + gid) * N_ + kv0;
        const float* sw1 = sw0 + 8 * N_;
        float mx0 = -3.4e38f, mx1 = -3.4e38f;
#pragma unroll
        for (int j = 0; j < 16; ++j) {
            float2 s0 = *(const float2*)&sw0[j * 8 + tg * 2];
            float2 s1 = *(const float2*)&sw1[j * 8 + tg * 2];
            acc[j][0] += s0.x; acc[j][1] += s0.y;
            acc[j][2] += s1.x; acc[j][3] += s1.y;
            mx0 = fmaxf(mx0, fmaxf(acc[j][0], acc[j][1]));
            mx1 = fmaxf(mx1, fmaxf(acc[j][2], acc[j][3]));
        }
#pragma unroll
        for (int o = 1; o <= 2; o <<= 1) {
            mx0 = fmaxf(mx0, __shfl_xor_sync(0xffffffffu, mx0, o));
            mx1 = fmaxf(mx1, __shfl_xor_sync(0xffffffffu, mx1, o));
        }

        const float mn0 = fmaxf(m0r, mx0), mn1 = fmaxf(m1r, mx1);
        const float sc0 = __expf(m0r - mn0), sc1 = __expf(m1r - mn1);
        m0r = mn0; m1r = mn1;

        float rs0 = 0.f, rs1 = 0.f;
        unsigned pr[16][2];
#pragma unroll
        for (int j = 0; j < 16; ++j) {
            float p0 = __expf(acc[j][0] - mn0);
            float p1 = __expf(acc[j][1] - mn0);
            float p2 = __expf(acc[j][2] - mn1);
            float p3 = __expf(acc[j][3] - mn1);
            rs0 += p0 + p1; rs1 += p2 + p3;
            pr[j][0] = pack2(p0, p1);
            pr[j][1] = pack2(p2, p3);
        }
#pragma unroll
        for (int o = 1; o <= 2; o <<= 1) {
            rs0 += __shfl_xor_sync(0xffffffffu, rs0, o);
            rs1 += __shfl_xor_sync(0xffffffffu, rs1, o);
        }
        l0 = l0 * sc0 + rs0;
        l1 = l1 * sc1 + rs1;

#pragma unroll
        for (int jo = 0; jo < 8; ++jo) {
            oacc[jo][0] *= sc0; oacc[jo][1] *= sc0;
            oacc[jo][2] *= sc1; oacc[jo][3] *= sc1;
        }
        // ---- O += P.V  (V loaded transposed by ldmatrix.trans) ----
#pragma unroll
        for (int kt2 = 0; kt2 < 8; ++kt2) {
            unsigned a0 = pr[2 * kt2][0],     a1 = pr[2 * kt2][1];
            unsigned a2 = pr[2 * kt2 + 1][0], a3 = pr[2 * kt2 + 1][1];
#pragma unroll
            for (int jo = 0; jo < 8; jo += 2) {
                unsigned r0, r1, r2, r3;  // bf[jo][0], bf[jo][1], bf[jo+1][0], bf[jo+1][1]
                ldm_x4t(r0, r1, r2, r3, vbb + (uint32_t)(((kt2 * 16) * 72 + jo * 8) * 2));
                mma_f16(oacc[jo],     a0, a1, a2, a3, r0, r1);
                mma_f16(oacc[jo + 1], a0, a1, a2, a3, r2, r3);
            }
        }
    }

    const float i0 = 1.f / l0, i1 = 1.f / l1;
    __half* o0 = outp + (long)(b * N_ + bm + m0 + gid) * D_ + h * DH_;
    __half* o1 = o0 + 8 * D_;
#pragma unroll
    for (int jo = 0; jo < 8; ++jo) {
        *(unsigned*)&o0[jo * 8 + tg * 2] = pack2(oacc[jo][0] * i0, oacc[jo][1] * i0);
        *(unsigned*)&o1[jo * 8 + tg * 2] = pack2(oacc[jo][2] * i1, oacc[jo][3] * i1);
    }
}

// ---------------- fp16 GEMM, BK=64, 2-stage cp.async + ldmatrix ---------------
// FLAGS: 1=bias 2=gelu 4=resid(fp32) 8=half-out 16=scale cols<768 by 1/8
#define G3_SK    72
#define G3_ATILE (128*G3_SK)
#define G3_STAGE (2*G3_ATILE)
#define G3_SMEM  (2*G3_STAGE*2)
template<int FLAGS>
__global__ void __launch_bounds__(256, 2)
gemm_h3(const __half* __restrict__ A, const __half* __restrict__ B,
        void* __restrict__ Cv, int K, int lda, int ldc,
        const float* __restrict__ bias,
        const float* __restrict__ resid, int ldres) {
    extern __shared__ __half sm3[];
    const int tid  = threadIdx.x;
    const int lane = tid & 31;
    const int gid  = lane >> 2;
    const int tg   = lane & 3;
    const int warp = tid >> 5;
    const int mwarp = (warp >> 2) * 64;
    const int nwarp = (warp & 3) * 32;
    const int bn = blockIdx.x * 128;
    const int bm = blockIdx.y * 128;

    const int lr = tid >> 3;
    const int lj = (tid & 7) * 8;
    const uint32_t smb = smem_u32(sm3);
    const __half* Apt = A + (long)(bm + lr) * lda + lj;
    const __half* Bpt = B + (long)(bn + lr) * K + lj;

    const int roff = (lane & 7) + ((lane >> 3) & 1) * 8;
    const int coff = ((lane >> 4) & 1) * 8;
    const uint32_t aAb = smb + (uint32_t)(((mwarp + roff) * G3_SK + coff) * 2);
    const uint32_t aBb = smb + (uint32_t)((G3_ATILE + (nwarp + roff) * G3_SK + coff) * 2);

    float acc[4][4][4] = {};
    const int T = K >> 6;

    auto load = [&](int t, int s) {
        const uint32_t oA = smb + s * (G3_STAGE * 2) + (lr * G3_SK + lj) * 2;
        const uint32_t oB = oA + G3_ATILE * 2;
        const long ko = (long)t * 64;
#pragma unroll
        for (int i = 0; i < 4; ++i) {
            asm volatile("cp.async.cg.shared.global [%0],[%1],16;"
                :: "r"(oA + i * 32 * G3_SK * 2), "l"(Apt + ko + (long)i * 32 * lda) : "memory");
            asm volatile("cp.async.cg.shared.global [%0],[%1],16;"
                :: "r"(oB + i * 32 * G3_SK * 2), "l"(Bpt + ko + (long)i * 32 * K) : "memory");
        }
        asm volatile("cp.async.commit_group;" ::: "memory");
    };

    load(0, 0);
    for (int t = 0; t < T; ++t) {
        const int s = t & 1;
        if (t + 1 < T) {
            load(t + 1, s ^ 1);
            asm volatile("cp.async.wait_group 1;" ::: "memory");
        } else {
            asm volatile("cp.async.wait_group 0;" ::: "memory");
        }
        __syncthreads();

        const uint32_t sb_ = (uint32_t)(s * G3_STAGE * 2);
#pragma unroll
        for (int ks = 0; ks < 4; ++ks) {
            unsigned af[4][4];
#pragma unroll
            for (int i = 0; i < 4; ++i)
                ldm_x4(af[i][0], af[i][1], af[i][2], af[i][3],
                       aAb + sb_ + (uint32_t)((i * 16 * G3_SK + ks * 16) * 2));
            unsigned bf[4][2];
#pragma unroll
            for (int jp = 0; jp < 4; jp += 2)
                ldm_x4(bf[jp][0], bf[jp + 1][0], bf[jp][1], bf[jp + 1][1],
                       aBb + sb_ + (uint32_t)((jp * 8 * G3_SK + ks * 16) * 2));
#pragma unroll
            for (int i = 0; i < 4; ++i)
#pragma unroll
                for (int j = 0; j < 4; ++j)
                    mma_f16(acc[i][j], af[i][0], af[i][1], af[i][2], af[i][3],
                            bf[j][0], bf[j][1]);
        }
        __syncthreads();
    }

    // ---- epilogue ----
#pragma unroll
    for (int i = 0; i < 4; ++i) {
        const int r0 = bm + mwarp + i * 16 + gid;
#pragma unroll
        for (int j = 0; j < 4; ++j) {
            const int c = bn + nwarp + j * 8 + tg * 2;
#pragma unroll
            for (int hh = 0; hh < 2; ++hh) {
                const int row = r0 + hh * 8;
                float2 p = make_float2(acc[i][j][hh * 2], acc[i][j][hh * 2 + 1]);
                if (FLAGS & 16) { const float sc = (c < D_) ? 0.125f : 1.f; p.x *= sc; p.y *= sc; }
                if (FLAGS & 1)  { p.x += bias[c]; p.y += bias[c + 1]; }
                if (FLAGS & 2)  {
                    p.x = 0.5f * p.x * (1.f + erff(p.x * 0.70710678118654752f));
                    p.y = 0.5f * p.y * (1.f + erff(p.y * 0.70710678118654752f));
                }
                if (FLAGS & 4)  {
                    float2 r = *(const float2*)&resid[(long)row * ldres + c];
                    p.x += r.x; p.y += r.y;
                }
                if (FLAGS & 8)
                    *(unsigned*)&((__half*)Cv)[(long)row * ldc + c] = pack2(p.x, p.y);
                else
                    *(float2*)&((float*)Cv)[(long)row * ldc + c] = p;
            }
        }
    }
}

// ---------------- launch ------------------------------------------------------
extern "C" void kernel_launch(void* const* d_in, const int* in_sizes, int n_in,
                              void* d_out, int out_size) {
    const float* x_in  = (const float*)d_in[0];
    const float* sw    = (const float*)d_in[1];
    const float* ln1g  = (const float*)d_in[2];
    const float* ln1b  = (const float*)d_in[3];
    const float* wqkv  = (const float*)d_in[4];
    const float* wout  = (const float*)d_in[5];
    const float* bout  = (const float*)d_in[6];
    const float* ln2g  = (const float*)d_in[7];
    const float* ln2b  = (const float*)d_in[8];
    const float* w1    = (const float*)d_in[9];
    const float* b1    = (const float*)d_in[10];
    const float* w2    = (const float*)d_in[11];
    const float* b2    = (const float*)d_in[12];
    float* out = (float*)d_out;

    float *px;
    __half *pxn, *pqkv, *patt, *ph, *pwT;
    cudaGetSymbolAddress((void**)&px,   g_x);
    cudaGetSymbolAddress((void**)&pxn,  g_xnh);
    cudaGetSymbolAddress((void**)&pqkv, g_qkvh);
    cudaGetSymbolAddress((void**)&patt, g_atth);
    cudaGetSymbolAddress((void**)&ph,   g_hh);
    cudaGetSymbolAddress((void**)&pwT,  g_whT);

    cudaFuncSetAttribute(flash_k, cudaFuncAttributeMaxDynamicSharedMemorySize, FL_SMEM);
    cudaFuncSetAttribute(gemm_h3<8|16>,  cudaFuncAttributeMaxDynamicSharedMemorySize, G3_SMEM);
    cudaFuncSetAttribute(gemm_h3<1|4>,   cudaFuncAttributeMaxDynamicSharedMemorySize, G3_SMEM);
    cudaFuncSetAttribute(gemm_h3<1|2|8>, cudaFuncAttributeMaxDynamicSharedMemorySize, G3_SMEM);

    tr_hL<<<dim3(D3/32, D_/32, L_),  dim3(32,8)>>>(wqkv, pwT + OFF_QKVT, D_, D3,
                                                   (long)D_*D3,  (long)WT_LSTR);
    tr_hL<<<dim3(D_/32, D_/32, L_),  dim3(32,8)>>>(wout, pwT + OFF_OWT,  D_, D_,
                                                   (long)D_*D_,  (long)WT_LSTR);
    tr_hL<<<dim3(DFF/32, D_/32, L_), dim3(32,8)>>>(w1,   pwT + OFF_W1T,  D_, DFF,
                                                   (long)D_*DFF, (long)WT_LSTR);
    tr_hL<<<dim3(D_/32, DFF/32, L_), dim3(32,8)>>>(w2,   pwT + OFF_W2T,  DFF, D_,
                                                   (long)DFF*D_, (long)WT_LSTR);

    for (int l = 0; l < L_; ++l) {
        const float* xcur = (l == 0) ? x_in : px;
        __half* wl = pwT + (size_t)l * WT_LSTR;

        ln_kernel<<<ROWS, 256>>>(xcur, ln1g + (long)l * D_, ln1b + (long)l * D_, pxn);

        gemm_h3<8|16><<<dim3(D3/128, ROWS/128), 256, G3_SMEM>>>(
            pxn, wl + OFF_QKVT, pqkv, D_, D_, D3, nullptr, nullptr, 0);

        flash_k<<<dim3(N_/128, ZHB), 256, FL_SMEM>>>(pqkv, sw, patt);

        gemm_h3<1|4><<<dim3(D_/128, ROWS/128), 256, G3_SMEM>>>(
            patt, wl + OFF_OWT, px, D_, D_, D_,
            bout + (long)l * D_, xcur, D_);

        ln_kernel<<<ROWS, 256>>>(px, ln2g + (long)l * D_, ln2b + (long)l * D_, pxn);

        gemm_h3<1|2|8><<<dim3(DFF/128, ROWS/128), 256, G3_SMEM>>>(
            pxn, wl + OFF_W1T, ph, D_, D_, DFF,
            b1 + (long)l * DFF, nullptr, 0);

        float* cdst = (l == L_ - 1) ? out : px;
        gemm_h3<1|4><<<dim3(D_/128, ROWS/128), 256, G3_SMEM>>>(
            ph, wl + OFF_W2T, cdst, DFF, DFF, D_,
            b2 + (long)l * D_, px, D_);
    }
}

// round 12
// speedup vs baseline: 6.4070x; 1.0431x over previous
#include <cuda_runtime.h>
#include <cuda_fp16.h>
#include <math.h>
#include <stdint.h>

#define D_   768
#define H_   12
#define L_   6
#define B_   4
#define N_   1024
#define DH_  64
#define ROWS (B_*N_)      /* 4096 */
#define D3   (3*D_)       /* 2304 */
#define DFF  (4*D_)       /* 3072 */
#define ZHB  (B_*H_)      /* 48   */

#define OFF_QKVT 0
#define OFF_OWT  (768*2304)
#define OFF_W1T  (OFF_OWT + 768*768)
#define OFF_W2T  (OFF_W1T + 768*3072)
#define WT_LSTR  (OFF_W2T + 3072*768)

// ---------------- scratch ----------------------------------------------------
__device__ float  g_x   [ROWS*(size_t)D_];
__device__ __half g_xnh [ROWS*(size_t)D_];
__device__ __half g_qkvh[ROWS*(size_t)D3];
__device__ __half g_atth[ROWS*(size_t)D_];
__device__ __half g_hh  [ROWS*(size_t)DFF];
__device__ __half g_whT [(size_t)L_*WT_LSTR];

__device__ __forceinline__ unsigned pack2(float x, float y) {
    __half2 h = __floats2half2_rn(x, y);
    return *reinterpret_cast<unsigned*>(&h);
}
__device__ __forceinline__ void mma_f16(float* c,
                                        unsigned a0, unsigned a1, unsigned a2, unsigned a3,
                                        unsigned b0, unsigned b1) {
    asm volatile(
        "mma.sync.aligned.m16n8k16.row.col.f32.f16.f16.f32 "
        "{%0,%1,%2,%3}, {%4,%5,%6,%7}, {%8,%9}, {%0,%1,%2,%3};"
        : "+f"(c[0]), "+f"(c[1]), "+f"(c[2]), "+f"(c[3])
        : "r"(a0), "r"(a1), "r"(a2), "r"(a3), "r"(b0), "r"(b1));
}
__device__ __forceinline__ uint32_t smem_u32(const void* p) {
    uint32_t a;
    asm("{ .reg .u64 t; cvta.to.shared.u64 t, %1; cvt.u32.u64 %0, t; }" : "=r"(a) : "l"(p));
    return a;
}
__device__ __forceinline__ void ldm_x4(unsigned& r0, unsigned& r1, unsigned& r2, unsigned& r3,
                                       uint32_t a) {
    asm volatile("ldmatrix.sync.aligned.m8n8.x4.shared.b16 {%0,%1,%2,%3}, [%4];"
        : "=r"(r0), "=r"(r1), "=r"(r2), "=r"(r3) : "r"(a));
}
__device__ __forceinline__ void ldm_x4t(unsigned& r0, unsigned& r1, unsigned& r2, unsigned& r3,
                                        uint32_t a) {
    asm volatile("ldmatrix.sync.aligned.m8n8.x4.trans.shared.b16 {%0,%1,%2,%3}, [%4];"
        : "=r"(r0), "=r"(r1), "=r"(r2), "=r"(r3) : "r"(a));
}
#define CP16(dst, src) \
    asm volatile("cp.async.cg.shared.global [%0],[%1],16;" :: "r"(dst), "l"(src) : "memory")

// ---------------- batched weight transpose+cvt (z = layer) --------------------
__global__ void tr_hL(const float* __restrict__ src, __half* __restrict__ dst,
                      int R, int C, long srcStr, long dstStr) {
    __shared__ float t[32][33];
    const float* s = src + (long)blockIdx.z * srcStr;
    __half*      d = dst + (long)blockIdx.z * dstStr;
    const int c0 = blockIdx.x * 32, r0 = blockIdx.y * 32;
    const int x = threadIdx.x, y = threadIdx.y;
#pragma unroll
    for (int i = 0; i < 32; i += 8)
        t[y + i][x] = s[(long)(r0 + y + i) * C + c0 + x];
    __syncthreads();
#pragma unroll
    for (int i = 0; i < 32; i += 8)
        d[(long)(c0 + y + i) * R + r0 + x] = __float2half(t[x][y + i]);
}

// ---------------- LayerNorm (fp32 in, fp16 out) --------------------------------
__global__ void ln_kernel(const float* __restrict__ x,
                          const float* __restrict__ g,
                          const float* __restrict__ b,
                          __half* __restrict__ y) {
    const int row = blockIdx.x;
    const float* xr = x + (size_t)row * D_;
    __half*      yr = y + (size_t)row * D_;
    const int tid = threadIdx.x;

    float v[3], s = 0.f, s2 = 0.f;
#pragma unroll
    for (int i = 0; i < 3; ++i) {
        float t = xr[tid + i * 256];
        v[i] = t; s += t; s2 += t * t;
    }
#pragma unroll
    for (int o = 16; o; o >>= 1) {
        s  += __shfl_xor_sync(0xffffffffu, s,  o);
        s2 += __shfl_xor_sync(0xffffffffu, s2, o);
    }
    __shared__ float shs[8], shs2[8];
    const int w = tid >> 5;
    if ((tid & 31) == 0) { shs[w] = s; shs2[w] = s2; }
    __syncthreads();
    s = 0.f; s2 = 0.f;
#pragma unroll
    for (int i = 0; i < 8; ++i) { s += shs[i]; s2 += shs2[i]; }
    const float mean = s * (1.f / D_);
    const float var  = s2 * (1.f / D_) - mean * mean;
    const float rstd = rsqrtf(var + 1e-5f);
#pragma unroll
    for (int i = 0; i < 3; ++i) {
        int c = tid + i * 256;
        yr[c] = __float2half((v[i] - mean) * rstd * g[c] + b[c]);
    }
}

// ---------------- fused flash attention (ldmatrix everywhere) -----------------
#define FL_SMEM (3*128*72*2)
__global__ void __launch_bounds__(256)
flash_k(const __half* __restrict__ qkv, const float* __restrict__ sw,
        __half* __restrict__ outp) {
    extern __shared__ __half sm[];
    __half (*Qs)[72] = (__half(*)[72]) sm;
    __half (*Ks)[72] = (__half(*)[72]) (sm + 128 * 72);
    __half (*Vs)[72] = (__half(*)[72]) (sm + 2 * 128 * 72);

    const int tid = threadIdx.x, lane = tid & 31;
    const int gid = lane >> 2, tg = lane & 3;
    const int warp = tid >> 5;
    const int m0 = warp * 16;
    const int bm = blockIdx.x * 128;
    const int z = blockIdx.y, b = z / H_, h = z - b * H_;

    const int roff = (lane & 7) + ((lane >> 3) & 1) * 8;
    const int coff = ((lane >> 4) & 1) * 8;

    const __half* Qg = qkv + ((long)(b * N_ + bm)) * D3 + h * DH_;
    const __half* Kg = qkv + (long)b * N_ * D3 + D_ + h * DH_;
    const __half* Vg = Kg + D_;
    const float* swb = sw + (long)b * N_ * N_;

#pragma unroll
    for (int i = 0; i < 4; ++i) {
        int flat = tid + i * 256;
        int r = flat >> 3, j = (flat & 7) * 8;
        *(uint4*)&Qs[r][j] = *(const uint4*)&Qg[(long)r * D3 + j];
    }

    const uint32_t qb  = smem_u32(sm) + (uint32_t)(((m0 + roff) * 72 + coff) * 2);
    const uint32_t kbb = smem_u32(sm) + (uint32_t)((128 * 72 + roff * 72 + coff) * 2);
    const uint32_t vbb = smem_u32(sm) + (uint32_t)((2 * 128 * 72 + roff * 72 + coff) * 2);

    float m0r = -3.4e38f, m1r = -3.4e38f, l0 = 0.f, l1 = 0.f;
    float oacc[8][4];
#pragma unroll
    for (int jo = 0; jo < 8; ++jo)
#pragma unroll
        for (int q = 0; q < 4; ++q) oacc[jo][q] = 0.f;

    for (int kv0 = 0; kv0 < N_; kv0 += 128) {
        __syncthreads();
#pragma unroll
        for (int i = 0; i < 4; ++i) {
            int flat = tid + i * 256;
            int r = flat >> 3, j = (flat & 7) * 8;
            *(uint4*)&Ks[r][j] = *(const uint4*)&Kg[(long)(kv0 + r) * D3 + j];
        }
#pragma unroll
        for (int i = 0; i < 4; ++i) {
            int flat = tid + i * 256;
            int r = flat >> 3, j = (flat & 7) * 8;
            *(uint4*)&Vs[r][j] = *(const uint4*)&Vg[(long)(kv0 + r) * D3 + j];
        }
        __syncthreads();

        float acc[16][4];
#pragma unroll
        for (int j = 0; j < 16; ++j)
#pragma unroll
            for (int q = 0; q < 4; ++q) acc[j][q] = 0.f;
#pragma unroll
        for (int kt = 0; kt < 4; ++kt) {
            unsigned a0, a1, a2, a3;
            ldm_x4(a0, a1, a2, a3, qb + kt * 32);
#pragma unroll
            for (int j = 0; j < 16; j += 2) {
                unsigned r0, r1, r2, r3;
                ldm_x4(r0, r1, r2, r3, kbb + (uint32_t)((j * 8 * 72 + kt * 16) * 2));
                mma_f16(acc[j],     a0, a1, a2, a3, r0, r2);
                mma_f16(acc[j + 1], a0, a1, a2, a3, r1, r3);
            }
        }

        const float* sw0 = swb + (long)(bm + m0 + gid) * N_ + kv0;
        const float* sw1 = sw0 + 8 * N_;
        float mx0 = -3.4e38f, mx1 = -3.4e38f;
#pragma unroll
        for (int j = 0; j < 16; ++j) {
            float2 s0 = *(const float2*)&sw0[j * 8 + tg * 2];
            float2 s1 = *(const float2*)&sw1[j * 8 + tg * 2];
            acc[j][0] += s0.x; acc[j][1] += s0.y;
            acc[j][2] += s1.x; acc[j][3] += s1.y;
            mx0 = fmaxf(mx0, fmaxf(acc[j][0], acc[j][1]));
            mx1 = fmaxf(mx1, fmaxf(acc[j][2], acc[j][3]));
        }
#pragma unroll
        for (int o = 1; o <= 2; o <<= 1) {
            mx0 = fmaxf(mx0, __shfl_xor_sync(0xffffffffu, mx0, o));
            mx1 = fmaxf(mx1, __shfl_xor_sync(0xffffffffu, mx1, o));
        }

        const float mn0 = fmaxf(m0r, mx0), mn1 = fmaxf(m1r, mx1);
        const float sc0 = __expf(m0r - mn0), sc1 = __expf(m1r - mn1);
        m0r = mn0; m1r = mn1;

        float rs0 = 0.f, rs1 = 0.f;
        unsigned pr[16][2];
#pragma unroll
        for (int j = 0; j < 16; ++j) {
            float p0 = __expf(acc[j][0] - mn0);
            float p1 = __expf(acc[j][1] - mn0);
            float p2 = __expf(acc[j][2] - mn1);
            float p3 = __expf(acc[j][3] - mn1);
            rs0 += p0 + p1; rs1 += p2 + p3;
            pr[j][0] = pack2(p0, p1);
            pr[j][1] = pack2(p2, p3);
        }
#pragma unroll
        for (int o = 1; o <= 2; o <<= 1) {
            rs0 += __shfl_xor_sync(0xffffffffu, rs0, o);
            rs1 += __shfl_xor_sync(0xffffffffu, rs1, o);
        }
        l0 = l0 * sc0 + rs0;
        l1 = l1 * sc1 + rs1;

#pragma unroll
        for (int jo = 0; jo < 8; ++jo) {
            oacc[jo][0] *= sc0; oacc[jo][1] *= sc0;
            oacc[jo][2] *= sc1; oacc[jo][3] *= sc1;
        }
#pragma unroll
        for (int kt2 = 0; kt2 < 8; ++kt2) {
            unsigned a0 = pr[2 * kt2][0],     a1 = pr[2 * kt2][1];
            unsigned a2 = pr[2 * kt2 + 1][0], a3 = pr[2 * kt2 + 1][1];
#pragma unroll
            for (int jo = 0; jo < 8; jo += 2) {
                unsigned r0, r1, r2, r3;
                ldm_x4t(r0, r1, r2, r3, vbb + (uint32_t)(((kt2 * 16) * 72 + jo * 8) * 2));
                mma_f16(oacc[jo],     a0, a1, a2, a3, r0, r1);
                mma_f16(oacc[jo + 1], a0, a1, a2, a3, r2, r3);
            }
        }
    }

    const float i0 = 1.f / l0, i1 = 1.f / l1;
    __half* o0 = outp + (long)(b * N_ + bm + m0 + gid) * D_ + h * DH_;
    __half* o1 = o0 + 8 * D_;
#pragma unroll
    for (int jo = 0; jo < 8; ++jo) {
        *(unsigned*)&o0[jo * 8 + tg * 2] = pack2(oacc[jo][0] * i0, oacc[jo][1] * i0);
        *(unsigned*)&o1[jo * 8 + tg * 2] = pack2(oacc[jo][2] * i1, oacc[jo][3] * i1);
    }
}

// ---------------- fp16 GEMM: BK=64, 3-stage cp.async, ldmatrix ----------------
// C[M,N] = A[M,K]h @ B[N,K]h^T.  8 warps as 2(m) x 4(n); warp tile (BM/2)x(BN/4).
// FLAGS: 1=bias 2=gelu 4=resid(fp32) 8=half-out 16=scale cols<768 by 1/8
#define G4_SK 72
template<int BM, int BN, int FLAGS>
__global__ void __launch_bounds__(256, 2)
gemm_h4(const __half* __restrict__ A, const __half* __restrict__ B,
        void* __restrict__ Cv, int K, int lda, int ldc,
        const float* __restrict__ bias,
        const float* __restrict__ resid, int ldres) {
    constexpr int ATILE = BM * G4_SK;               // halfs
    constexpr int STAGE = (BM + BN) * G4_SK;        // halfs
    constexpr int WM = BM / 2, WN = BN / 4;
    constexpr int FM = WM / 16, FN = WN / 8;
    extern __shared__ __half sm4[];

    const int tid  = threadIdx.x;
    const int lane = tid & 31;
    const int gid  = lane >> 2;
    const int tg   = lane & 3;
    const int warp = tid >> 5;
    const int mwarp = (warp >> 2) * WM;
    const int nwarp = (warp & 3) * WN;
    const int bn = blockIdx.x * BN;
    const int bm = blockIdx.y * BM;

    const uint32_t smb = smem_u32(sm4);
    const int roff = (lane & 7) + ((lane >> 3) & 1) * 8;
    const int coff = ((lane >> 4) & 1) * 8;
    const uint32_t aAb = smb + (uint32_t)(((mwarp + roff) * G4_SK + coff) * 2);
    const uint32_t aBb = smb + (uint32_t)((ATILE + (nwarp + roff) * G4_SK + coff) * 2);

    float acc[FM][FN][4] = {};
    const int T = K >> 6;

    auto load = [&](int t, int s) {
        const uint32_t base = smb + (uint32_t)(s * STAGE * 2);
        const long ko = (long)t * 64;
#pragma unroll
        for (int i = 0; i < BM * 8 / 256; ++i) {
            int flat = tid + i * 256;
            int r = flat >> 3, c = (flat & 7) * 8;
            CP16(base + (uint32_t)((r * G4_SK + c) * 2),
                 A + (long)(bm + r) * lda + ko + c);
        }
#pragma unroll
        for (int i = 0; i < BN * 8 / 256; ++i) {
            int flat = tid + i * 256;
            int r = flat >> 3, c = (flat & 7) * 8;
            CP16(base + (uint32_t)((ATILE + r * G4_SK + c) * 2),
                 B + (long)(bn + r) * K + ko + c);
        }
        asm volatile("cp.async.commit_group;" ::: "memory");
    };

    load(0, 0);
    if (T > 1) load(1, 1);
    for (int t = 0; t < T; ++t) {
        const int s = t % 3;
        if (t + 1 < T) asm volatile("cp.async.wait_group 1;" ::: "memory");
        else           asm volatile("cp.async.wait_group 0;" ::: "memory");
        __syncthreads();
        if (t + 2 < T) load(t + 2, (t + 2) % 3);

        const uint32_t sb_ = (uint32_t)(s * STAGE * 2);
#pragma unroll
        for (int ks = 0; ks < 4; ++ks) {
            unsigned af[FM][4];
#pragma unroll
            for (int i = 0; i < FM; ++i)
                ldm_x4(af[i][0], af[i][1], af[i][2], af[i][3],
                       aAb + sb_ + (uint32_t)((i * 16 * G4_SK + ks * 16) * 2));
            unsigned bf[FN][2];
#pragma unroll
            for (int jp = 0; jp < FN; jp += 2)
                ldm_x4(bf[jp][0], bf[jp + 1][0], bf[jp][1], bf[jp + 1][1],
                       aBb + sb_ + (uint32_t)((jp * 8 * G4_SK + ks * 16) * 2));
#pragma unroll
            for (int i = 0; i < FM; ++i)
#pragma unroll
                for (int j = 0; j < FN; ++j)
                    mma_f16(acc[i][j], af[i][0], af[i][1], af[i][2], af[i][3],
                            bf[j][0], bf[j][1]);
        }
        __syncthreads();
    }

    // ---- epilogue ----
#pragma unroll
    for (int i = 0; i < FM; ++i) {
        const int r0 = bm + mwarp + i * 16 + gid;
#pragma unroll
        for (int j = 0; j < FN; ++j) {
            const int c = bn + nwarp + j * 8 + tg * 2;
#pragma unroll
            for (int hh = 0; hh < 2; ++hh) {
                const int row = r0 + hh * 8;
                float2 p = make_float2(acc[i][j][hh * 2], acc[i][j][hh * 2 + 1]);
                if (FLAGS & 16) { const float sc = (c < D_) ? 0.125f : 1.f; p.x *= sc; p.y *= sc; }
                if (FLAGS & 1)  { p.x += bias[c]; p.y += bias[c + 1]; }
                if (FLAGS & 2)  {
                    p.x = 0.5f * p.x * (1.f + erff(p.x * 0.70710678118654752f));
                    p.y = 0.5f * p.y * (1.f + erff(p.y * 0.70710678118654752f));
                }
                if (FLAGS & 4)  {
                    float2 r = *(const float2*)&resid[(long)row * ldres + c];
                    p.x += r.x; p.y += r.y;
                }
                if (FLAGS & 8)
                    *(unsigned*)&((__half*)Cv)[(long)row * ldc + c] = pack2(p.x, p.y);
                else
                    *(float2*)&((float*)Cv)[(long)row * ldc + c] = p;
            }
        }
    }
}

// ---------------- launch ------------------------------------------------------
extern "C" void kernel_launch(void* const* d_in, const int* in_sizes, int n_in,
                              void* d_out, int out_size) {
    const float* x_in  = (const float*)d_in[0];
    const float* sw    = (const float*)d_in[1];
    const float* ln1g  = (const float*)d_in[2];
    const float* ln1b  = (const float*)d_in[3];
    const float* wqkv  = (const float*)d_in[4];
    const float* wout  = (const float*)d_in[5];
    const float* bout  = (const float*)d_in[6];
    const float* ln2g  = (const float*)d_in[7];
    const float* ln2b  = (const float*)d_in[8];
    const float* w1    = (const float*)d_in[9];
    const float* b1    = (const float*)d_in[10];
    const float* w2    = (const float*)d_in[11];
    const float* b2    = (const float*)d_in[12];
    float* out = (float*)d_out;

    float *px;
    __half *pxn, *pqkv, *patt, *ph, *pwT;
    cudaGetSymbolAddress((void**)&px,   g_x);
    cudaGetSymbolAddress((void**)&pxn,  g_xnh);
    cudaGetSymbolAddress((void**)&pqkv, g_qkvh);
    cudaGetSymbolAddress((void**)&patt, g_atth);
    cudaGetSymbolAddress((void**)&ph,   g_hh);
    cudaGetSymbolAddress((void**)&pwT,  g_whT);

    const int SM128 = 3 * (128 + 128) * G4_SK * 2;   // 110592 B
    const int SM64  = 3 * (64 + 128) * G4_SK * 2;    //  82944 B
    cudaFuncSetAttribute(flash_k, cudaFuncAttributeMaxDynamicSharedMemorySize, FL_SMEM);
    cudaFuncSetAttribute(gemm_h4<128,128,8|16>,  cudaFuncAttributeMaxDynamicSharedMemorySize, SM128);
    cudaFuncSetAttribute(gemm_h4<128,128,1|2|8>, cudaFuncAttributeMaxDynamicSharedMemorySize, SM128);
    cudaFuncSetAttribute(gemm_h4<64,128,1|4>,    cudaFuncAttributeMaxDynamicSharedMemorySize, SM64);

    tr_hL<<<dim3(D3/32, D_/32, L_),  dim3(32,8)>>>(wqkv, pwT + OFF_QKVT, D_, D3,
                                                   (long)D_*D3,  (long)WT_LSTR);
    tr_hL<<<dim3(D_/32, D_/32, L_),  dim3(32,8)>>>(wout, pwT + OFF_OWT,  D_, D_,
                                                   (long)D_*D_,  (long)WT_LSTR);
    tr_hL<<<dim3(DFF/32, D_/32, L_), dim3(32,8)>>>(w1,   pwT + OFF_W1T,  D_, DFF,
                                                   (long)D_*DFF, (long)WT_LSTR);
    tr_hL<<<dim3(D_/32, DFF/32, L_), dim3(32,8)>>>(w2,   pwT + OFF_W2T,  DFF, D_,
                                                   (long)DFF*D_, (long)WT_LSTR);

    for (int l = 0; l < L_; ++l) {
        const float* xcur = (l == 0) ? x_in : px;
        __half* wl = pwT + (size_t)l * WT_LSTR;

        ln_kernel<<<ROWS, 256>>>(xcur, ln1g + (long)l * D_, ln1b + (long)l * D_, pxn);

        // QKV (Q pre-scaled 1/8): 128x128 tiles, 576 CTAs
        gemm_h4<128,128,8|16><<<dim3(D3/128, ROWS/128), 256, SM128>>>(
            pxn, wl + OFF_QKVT, pqkv, D_, D_, D3, nullptr, nullptr, 0);

        flash_k<<<dim3(N_/128, ZHB), 256, FL_SMEM>>>(pqkv, sw, patt);

        // proj + bias + residual: 64x128 tiles, 384 CTAs
        gemm_h4<64,128,1|4><<<dim3(D_/128, ROWS/64), 256, SM64>>>(
            patt, wl + OFF_OWT, px, D_, D_, D_,
            bout + (long)l * D_, xcur, D_);

        ln_kernel<<<ROWS, 256>>>(px, ln2g + (long)l * D_, ln2b + (long)l * D_, pxn);

        // FC1 + bias + GELU: 128x128 tiles, 768 CTAs
        gemm_h4<128,128,1|2|8><<<dim3(DFF/128, ROWS/128), 256, SM128>>>(
            pxn, wl + OFF_W1T, ph, D_, D_, DFF,
            b1 + (long)l * DFF, nullptr, 0);

        // FC2 + bias + residual: 64x128 tiles, 384 CTAs (last layer -> d_out)
        float* cdst = (l == L_ - 1) ? out : px;
        gemm_h4<64,128,1|4><<<dim3(D_/128, ROWS/64), 256, SM64>>>(
            ph, wl + OFF_W2T, cdst, DFF, DFF, D_,
            b2 + (long)l * D_, px, D_);
    }
}

// round 13
// speedup vs baseline: 6.6454x; 1.0372x over previous
#include <cuda_runtime.h>
#include <cuda_fp16.h>
#include <math.h>
#include <stdint.h>

#define D_   768
#define H_   12
#define L_   6
#define B_   4
#define N_   1024
#define DH_  64
#define ROWS (B_*N_)      /* 4096 */
#define D3   (3*D_)       /* 2304 */
#define DFF  (4*D_)       /* 3072 */
#define ZHB  (B_*H_)      /* 48   */

#define OFF_QKVT 0
#define OFF_OWT  (768*2304)
#define OFF_W1T  (OFF_OWT + 768*768)
#define OFF_W2T  (OFF_W1T + 768*3072)
#define WT_LSTR  (OFF_W2T + 3072*768)

// ---------------- scratch ----------------------------------------------------
__device__ float  g_x   [ROWS*(size_t)D_];
__device__ __half g_xnh [ROWS*(size_t)D_];
__device__ __half g_qkvh[ROWS*(size_t)D3];
__device__ __half g_atth[ROWS*(size_t)D_];
__device__ __half g_hh  [ROWS*(size_t)DFF];
__device__ __half g_whT [(size_t)L_*WT_LSTR];

__device__ __forceinline__ unsigned pack2(float x, float y) {
    __half2 h = __floats2half2_rn(x, y);
    return *reinterpret_cast<unsigned*>(&h);
}
__device__ __forceinline__ void mma_f16(float* c,
                                        unsigned a0, unsigned a1, unsigned a2, unsigned a3,
                                        unsigned b0, unsigned b1) {
    asm volatile(
        "mma.sync.aligned.m16n8k16.row.col.f32.f16.f16.f32 "
        "{%0,%1,%2,%3}, {%4,%5,%6,%7}, {%8,%9}, {%0,%1,%2,%3};"
        : "+f"(c[0]), "+f"(c[1]), "+f"(c[2]), "+f"(c[3])
        : "r"(a0), "r"(a1), "r"(a2), "r"(a3), "r"(b0), "r"(b1));
}
__device__ __forceinline__ uint32_t smem_u32(const void* p) {
    uint32_t a;
    asm("{ .reg .u64 t; cvta.to.shared.u64 t, %1; cvt.u32.u64 %0, t; }" : "=r"(a) : "l"(p));
    return a;
}
__device__ __forceinline__ void ldm_x4(unsigned& r0, unsigned& r1, unsigned& r2, unsigned& r3,
                                       uint32_t a) {
    asm volatile("ldmatrix.sync.aligned.m8n8.x4.shared.b16 {%0,%1,%2,%3}, [%4];"
        : "=r"(r0), "=r"(r1), "=r"(r2), "=r"(r3) : "r"(a));
}
__device__ __forceinline__ void ldm_x4t(unsigned& r0, unsigned& r1, unsigned& r2, unsigned& r3,
                                        uint32_t a) {
    asm volatile("ldmatrix.sync.aligned.m8n8.x4.trans.shared.b16 {%0,%1,%2,%3}, [%4];"
        : "=r"(r0), "=r"(r1), "=r"(r2), "=r"(r3) : "r"(a));
}
#define CP16(dst, src) \
    asm volatile("cp.async.cg.shared.global [%0],[%1],16;" :: "r"(dst), "l"(src) : "memory")

// ---------------- batched weight transpose+cvt (z = layer) --------------------
__global__ void tr_hL(const float* __restrict__ src, __half* __restrict__ dst,
                      int R, int C, long srcStr, long dstStr) {
    __shared__ float t[32][33];
    const float* s = src + (long)blockIdx.z * srcStr;
    __half*      d = dst + (long)blockIdx.z * dstStr;
    const int c0 = blockIdx.x * 32, r0 = blockIdx.y * 32;
    const int x = threadIdx.x, y = threadIdx.y;
#pragma unroll
    for (int i = 0; i < 32; i += 8)
        t[y + i][x] = s[(long)(r0 + y + i) * C + c0 + x];
    __syncthreads();
#pragma unroll
    for (int i = 0; i < 32; i += 8)
        d[(long)(c0 + y + i) * R + r0 + x] = __float2half(t[x][y + i]);
}

// ---------------- LayerNorm (fp32 in, fp16 out) --------------------------------
__global__ void ln_kernel(const float* __restrict__ x,
                          const float* __restrict__ g,
                          const float* __restrict__ b,
                          __half* __restrict__ y) {
    const int row = blockIdx.x;
    const float* xr = x + (size_t)row * D_;
    __half*      yr = y + (size_t)row * D_;
    const int tid = threadIdx.x;

    float v[3], s = 0.f, s2 = 0.f;
#pragma unroll
    for (int i = 0; i < 3; ++i) {
        float t = xr[tid + i * 256];
        v[i] = t; s += t; s2 += t * t;
    }
#pragma unroll
    for (int o = 16; o; o >>= 1) {
        s  += __shfl_xor_sync(0xffffffffu, s,  o);
        s2 += __shfl_xor_sync(0xffffffffu, s2, o);
    }
    __shared__ float shs[8], shs2[8];
    const int w = tid >> 5;
    if ((tid & 31) == 0) { shs[w] = s; shs2[w] = s2; }
    __syncthreads();
    s = 0.f; s2 = 0.f;
#pragma unroll
    for (int i = 0; i < 8; ++i) { s += shs[i]; s2 += shs2[i]; }
    const float mean = s * (1.f / D_);
    const float var  = s2 * (1.f / D_) - mean * mean;
    const float rstd = rsqrtf(var + 1e-5f);
#pragma unroll
    for (int i = 0; i < 3; ++i) {
        int c = tid + i * 256;
        yr[c] = __float2half((v[i] - mean) * rstd * g[c] + b[c]);
    }
}

// ---------------- fused flash attention (unchanged from R12) ------------------
#define FL_SMEM (3*128*72*2)
__global__ void __launch_bounds__(256)
flash_k(const __half* __restrict__ qkv, const float* __restrict__ sw,
        __half* __restrict__ outp) {
    extern __shared__ __half sm[];
    __half (*Qs)[72] = (__half(*)[72]) sm;
    __half (*Ks)[72] = (__half(*)[72]) (sm + 128 * 72);
    __half (*Vs)[72] = (__half(*)[72]) (sm + 2 * 128 * 72);

    const int tid = threadIdx.x, lane = tid & 31;
    const int gid = lane >> 2, tg = lane & 3;
    const int warp = tid >> 5;
    const int m0 = warp * 16;
    const int bm = blockIdx.x * 128;
    const int z = blockIdx.y, b = z / H_, h = z - b * H_;

    const int roff = (lane & 7) + ((lane >> 3) & 1) * 8;
    const int coff = ((lane >> 4) & 1) * 8;

    const __half* Qg = qkv + ((long)(b * N_ + bm)) * D3 + h * DH_;
    const __half* Kg = qkv + (long)b * N_ * D3 + D_ + h * DH_;
    const __half* Vg = Kg + D_;
    const float* swb = sw + (long)b * N_ * N_;

#pragma unroll
    for (int i = 0; i < 4; ++i) {
        int flat = tid + i * 256;
        int r = flat >> 3, j = (flat & 7) * 8;
        *(uint4*)&Qs[r][j] = *(const uint4*)&Qg[(long)r * D3 + j];
    }

    const uint32_t qb  = smem_u32(sm) + (uint32_t)(((m0 + roff) * 72 + coff) * 2);
    const uint32_t kbb = smem_u32(sm) + (uint32_t)((128 * 72 + roff * 72 + coff) * 2);
    const uint32_t vbb = smem_u32(sm) + (uint32_t)((2 * 128 * 72 + roff * 72 + coff) * 2);

    float m0r = -3.4e38f, m1r = -3.4e38f, l0 = 0.f, l1 = 0.f;
    float oacc[8][4];
#pragma unroll
    for (int jo = 0; jo < 8; ++jo)
#pragma unroll
        for (int q = 0; q < 4; ++q) oacc[jo][q] = 0.f;

    for (int kv0 = 0; kv0 < N_; kv0 += 128) {
        __syncthreads();
#pragma unroll
        for (int i = 0; i < 4; ++i) {
            int flat = tid + i * 256;
            int r = flat >> 3, j = (flat & 7) * 8;
            *(uint4*)&Ks[r][j] = *(const uint4*)&Kg[(long)(kv0 + r) * D3 + j];
        }
#pragma unroll
        for (int i = 0; i < 4; ++i) {
            int flat = tid + i * 256;
            int r = flat >> 3, j = (flat & 7) * 8;
            *(uint4*)&Vs[r][j] = *(const uint4*)&Vg[(long)(kv0 + r) * D3 + j];
        }
        __syncthreads();

        float acc[16][4];
#pragma unroll
        for (int j = 0; j < 16; ++j)
#pragma unroll
            for (int q = 0; q < 4; ++q) acc[j][q] = 0.f;
#pragma unroll
        for (int kt = 0; kt < 4; ++kt) {
            unsigned a0, a1, a2, a3;
            ldm_x4(a0, a1, a2, a3, qb + kt * 32);
#pragma unroll
            for (int j = 0; j < 16; j += 2) {
                unsigned r0, r1, r2, r3;
                ldm_x4(r0, r1, r2, r3, kbb + (uint32_t)((j * 8 * 72 + kt * 16) * 2));
                mma_f16(acc[j],     a0, a1, a2, a3, r0, r2);
                mma_f16(acc[j + 1], a0, a1, a2, a3, r1, r3);
            }
        }

        const float* sw0 = swb + (long)(bm + m0 + gid) * N_ + kv0;
        const float* sw1 = sw0 + 8 * N_;
        float mx0 = -3.4e38f, mx1 = -3.4e38f;
#pragma unroll
        for (int j = 0; j < 16; ++j) {
            float2 s0 = *(const float2*)&sw0[j * 8 + tg * 2];
            float2 s1 = *(const float2*)&sw1[j * 8 + tg * 2];
            acc[j][0] += s0.x; acc[j][1] += s0.y;
            acc[j][2] += s1.x; acc[j][3] += s1.y;
            mx0 = fmaxf(mx0, fmaxf(acc[j][0], acc[j][1]));
            mx1 = fmaxf(mx1, fmaxf(acc[j][2], acc[j][3]));
        }
#pragma unroll
        for (int o = 1; o <= 2; o <<= 1) {
            mx0 = fmaxf(mx0, __shfl_xor_sync(0xffffffffu, mx0, o));
            mx1 = fmaxf(mx1, __shfl_xor_sync(0xffffffffu, mx1, o));
        }

        const float mn0 = fmaxf(m0r, mx0), mn1 = fmaxf(m1r, mx1);
        const float sc0 = __expf(m0r - mn0), sc1 = __expf(m1r - mn1);
        m0r = mn0; m1r = mn1;

        float rs0 = 0.f, rs1 = 0.f;
        unsigned pr[16][2];
#pragma unroll
        for (int j = 0; j < 16; ++j) {
            float p0 = __expf(acc[j][0] - mn0);
            float p1 = __expf(acc[j][1] - mn0);
            float p2 = __expf(acc[j][2] - mn1);
            float p3 = __expf(acc[j][3] - mn1);
            rs0 += p0 + p1; rs1 += p2 + p3;
            pr[j][0] = pack2(p0, p1);
            pr[j][1] = pack2(p2, p3);
        }
#pragma unroll
        for (int o = 1; o <= 2; o <<= 1) {
            rs0 += __shfl_xor_sync(0xffffffffu, rs0, o);
            rs1 += __shfl_xor_sync(0xffffffffu, rs1, o);
        }
        l0 = l0 * sc0 + rs0;
        l1 = l1 * sc1 + rs1;

#pragma unroll
        for (int jo = 0; jo < 8; ++jo) {
            oacc[jo][0] *= sc0; oacc[jo][1] *= sc0;
            oacc[jo][2] *= sc1; oacc[jo][3] *= sc1;
        }
#pragma unroll
        for (int kt2 = 0; kt2 < 8; ++kt2) {
            unsigned a0 = pr[2 * kt2][0],     a1 = pr[2 * kt2][1];
            unsigned a2 = pr[2 * kt2 + 1][0], a3 = pr[2 * kt2 + 1][1];
#pragma unroll
            for (int jo = 0; jo < 8; jo += 2) {
                unsigned r0, r1, r2, r3;
                ldm_x4t(r0, r1, r2, r3, vbb + (uint32_t)(((kt2 * 16) * 72 + jo * 8) * 2));
                mma_f16(oacc[jo],     a0, a1, a2, a3, r0, r1);
                mma_f16(oacc[jo + 1], a0, a1, a2, a3, r2, r3);
            }
        }
    }

    const float i0 = 1.f / l0, i1 = 1.f / l1;
    __half* o0 = outp + (long)(b * N_ + bm + m0 + gid) * D_ + h * DH_;
    __half* o1 = o0 + 8 * D_;
#pragma unroll
    for (int jo = 0; jo < 8; ++jo) {
        *(unsigned*)&o0[jo * 8 + tg * 2] = pack2(oacc[jo][0] * i0, oacc[jo][1] * i0);
        *(unsigned*)&o1[jo * 8 + tg * 2] = pack2(oacc[jo][2] * i1, oacc[jo][3] * i1);
    }
}

// ---------------- fp16 GEMM: 64x128xBK64, 2-stage, 3 CTAs/SM ------------------
// C[M,N] = A[M,K]h @ B[N,K]h^T. 8 warps as 2(m)x4(n); warp tile 32x32.
// FLAGS: 1=bias 2=gelu 4=resid(fp32) 8=half-out 16=scale cols<768 by 1/8
#define G5_SK    72
#define G5_BM    64
#define G5_BN    128
#define G5_ATILE (G5_BM*G5_SK)
#define G5_STAGE ((G5_BM+G5_BN)*G5_SK)
#define G5_SMEM  (2*G5_STAGE*2)            /* 55296 bytes */
template<int FLAGS>
__global__ void __launch_bounds__(256, 3)
gemm_h5(const __half* __restrict__ A, const __half* __restrict__ B,
        void* __restrict__ Cv, int K, int lda, int ldc,
        const float* __restrict__ bias,
        const float* __restrict__ resid, int ldres) {
    extern __shared__ __half sm5[];
    const int tid  = threadIdx.x;
    const int lane = tid & 31;
    const int gid  = lane >> 2;
    const int tg   = lane & 3;
    const int warp = tid >> 5;
    const int mwarp = (warp >> 2) * 32;
    const int nwarp = (warp & 3) * 32;
    const int bn = blockIdx.x * G5_BN;
    const int bm = blockIdx.y * G5_BM;

    const uint32_t smb = smem_u32(sm5);
    const int roff = (lane & 7) + ((lane >> 3) & 1) * 8;
    const int coff = ((lane >> 4) & 1) * 8;
    const uint32_t aAb = smb + (uint32_t)(((mwarp + roff) * G5_SK + coff) * 2);
    const uint32_t aBb = smb + (uint32_t)((G5_ATILE + (nwarp + roff) * G5_SK + coff) * 2);

    float acc[2][4][4] = {};
    const int T = K >> 6;

    auto load = [&](int t, int s) {
        const uint32_t base = smb + (uint32_t)(s * G5_STAGE * 2);
        const long ko = (long)t * 64;
#pragma unroll
        for (int i = 0; i < 2; ++i) {           // A: 64 rows x 8 chunks
            int flat = tid + i * 256;
            int r = flat >> 3, c = (flat & 7) * 8;
            CP16(base + (uint32_t)((r * G5_SK + c) * 2),
                 A + (long)(bm + r) * lda + ko + c);
        }
#pragma unroll
        for (int i = 0; i < 4; ++i) {           // B: 128 rows x 8 chunks
            int flat = tid + i * 256;
            int r = flat >> 3, c = (flat & 7) * 8;
            CP16(base + (uint32_t)((G5_ATILE + r * G5_SK + c) * 2),
                 B + (long)(bn + r) * K + ko + c);
        }
        asm volatile("cp.async.commit_group;" ::: "memory");
    };

    load(0, 0);
    for (int t = 0; t < T; ++t) {
        const int s = t & 1;
        if (t + 1 < T) {
            load(t + 1, s ^ 1);
            asm volatile("cp.async.wait_group 1;" ::: "memory");
        } else {
            asm volatile("cp.async.wait_group 0;" ::: "memory");
        }
        __syncthreads();

        const uint32_t sb_ = (uint32_t)(s * G5_STAGE * 2);
#pragma unroll
        for (int ks = 0; ks < 4; ++ks) {
            unsigned af[2][4];
#pragma unroll
            for (int i = 0; i < 2; ++i)
                ldm_x4(af[i][0], af[i][1], af[i][2], af[i][3],
                       aAb + sb_ + (uint32_t)((i * 16 * G5_SK + ks * 16) * 2));
            unsigned bf[4][2];
#pragma unroll
            for (int jp = 0; jp < 4; jp += 2)
                ldm_x4(bf[jp][0], bf[jp + 1][0], bf[jp][1], bf[jp + 1][1],
                       aBb + sb_ + (uint32_t)((jp * 8 * G5_SK + ks * 16) * 2));
#pragma unroll
            for (int i = 0; i < 2; ++i)
#pragma unroll
                for (int j = 0; j < 4; ++j)
                    mma_f16(acc[i][j], af[i][0], af[i][1], af[i][2], af[i][3],
                            bf[j][0], bf[j][1]);
        }
        __syncthreads();
    }

    // ---- epilogue ----
#pragma unroll
    for (int i = 0; i < 2; ++i) {
        const int r0 = bm + mwarp + i * 16 + gid;
#pragma unroll
        for (int j = 0; j < 4; ++j) {
            const int c = bn + nwarp + j * 8 + tg * 2;
#pragma unroll
            for (int hh = 0; hh < 2; ++hh) {
                const int row = r0 + hh * 8;
                float2 p = make_float2(acc[i][j][hh * 2], acc[i][j][hh * 2 + 1]);
                if (FLAGS & 16) { const float sc = (c < D_) ? 0.125f : 1.f; p.x *= sc; p.y *= sc; }
                if (FLAGS & 1)  { p.x += bias[c]; p.y += bias[c + 1]; }
                if (FLAGS & 2)  {
                    p.x = 0.5f * p.x * (1.f + erff(p.x * 0.70710678118654752f));
                    p.y = 0.5f * p.y * (1.f + erff(p.y * 0.70710678118654752f));
                }
                if (FLAGS & 4)  {
                    float2 r = *(const float2*)&resid[(long)row * ldres + c];
                    p.x += r.x; p.y += r.y;
                }
                if (FLAGS & 8)
                    *(unsigned*)&((__half*)Cv)[(long)row * ldc + c] = pack2(p.x, p.y);
                else
                    *(float2*)&((float*)Cv)[(long)row * ldc + c] = p;
            }
        }
    }
}

// ---------------- launch ------------------------------------------------------
extern "C" void kernel_launch(void* const* d_in, const int* in_sizes, int n_in,
                              void* d_out, int out_size) {
    const float* x_in  = (const float*)d_in[0];
    const float* sw    = (const float*)d_in[1];
    const float* ln1g  = (const float*)d_in[2];
    const float* ln1b  = (const float*)d_in[3];
    const float* wqkv  = (const float*)d_in[4];
    const float* wout  = (const float*)d_in[5];
    const float* bout  = (const float*)d_in[6];
    const float* ln2g  = (const float*)d_in[7];
    const float* ln2b  = (const float*)d_in[8];
    const float* w1    = (const float*)d_in[9];
    const float* b1    = (const float*)d_in[10];
    const float* w2    = (const float*)d_in[11];
    const float* b2    = (const float*)d_in[12];
    float* out = (float*)d_out;

    float *px;
    __half *pxn, *pqkv, *patt, *ph, *pwT;
    cudaGetSymbolAddress((void**)&px,   g_x);
    cudaGetSymbolAddress((void**)&pxn,  g_xnh);
    cudaGetSymbolAddress((void**)&pqkv, g_qkvh);
    cudaGetSymbolAddress((void**)&patt, g_atth);
    cudaGetSymbolAddress((void**)&ph,   g_hh);
    cudaGetSymbolAddress((void**)&pwT,  g_whT);

    cudaFuncSetAttribute(flash_k, cudaFuncAttributeMaxDynamicSharedMemorySize, FL_SMEM);
    cudaFuncSetAttribute(gemm_h5<8|16>,  cudaFuncAttributeMaxDynamicSharedMemorySize, G5_SMEM);
    cudaFuncSetAttribute(gemm_h5<1|4>,   cudaFuncAttributeMaxDynamicSharedMemorySize, G5_SMEM);
    cudaFuncSetAttribute(gemm_h5<1|2|8>, cudaFuncAttributeMaxDynamicSharedMemorySize, G5_SMEM);

    tr_hL<<<dim3(D3/32, D_/32, L_),  dim3(32,8)>>>(wqkv, pwT + OFF_QKVT, D_, D3,
                                                   (long)D_*D3,  (long)WT_LSTR);
    tr_hL<<<dim3(D_/32, D_/32, L_),  dim3(32,8)>>>(wout, pwT + OFF_OWT,  D_, D_,
                                                   (long)D_*D_,  (long)WT_LSTR);
    tr_hL<<<dim3(DFF/32, D_/32, L_), dim3(32,8)>>>(w1,   pwT + OFF_W1T,  D_, DFF,
                                                   (long)D_*DFF, (long)WT_LSTR);
    tr_hL<<<dim3(D_/32, DFF/32, L_), dim3(32,8)>>>(w2,   pwT + OFF_W2T,  DFF, D_,
                                                   (long)DFF*D_, (long)WT_LSTR);

    for (int l = 0; l < L_; ++l) {
        const float* xcur = (l == 0) ? x_in : px;
        __half* wl = pwT + (size_t)l * WT_LSTR;

        ln_kernel<<<ROWS, 256>>>(xcur, ln1g + (long)l * D_, ln1b + (long)l * D_, pxn);

        // QKV (Q pre-scaled 1/8): 1152 CTAs
        gemm_h5<8|16><<<dim3(D3/128, ROWS/64), 256, G5_SMEM>>>(
            pxn, wl + OFF_QKVT, pqkv, D_, D_, D3, nullptr, nullptr, 0);

        flash_k<<<dim3(N_/128, ZHB), 256, FL_SMEM>>>(pqkv, sw, patt);

        // proj + bias + residual: 384 CTAs
        gemm_h5<1|4><<<dim3(D_/128, ROWS/64), 256, G5_SMEM>>>(
            patt, wl + OFF_OWT, px, D_, D_, D_,
            bout + (long)l * D_, xcur, D_);

        ln_kernel<<<ROWS, 256>>>(px, ln2g + (long)l * D_, ln2b + (long)l * D_, pxn);

        // FC1 + bias + GELU: 1536 CTAs
        gemm_h5<1|2|8><<<dim3(DFF/128, ROWS/64), 256, G5_SMEM>>>(
            pxn, wl + OFF_W1T, ph, D_, D_, DFF,
            b1 + (long)l * DFF, nullptr, 0);

        // FC2 + bias + residual: 384 CTAs (last layer -> d_out)
        float* cdst = (l == L_ - 1) ? out : px;
        gemm_h5<1|4><<<dim3(D_/128, ROWS/64), 256, G5_SMEM>>>(
            ph, wl + OFF_W2T, cdst, DFF, DFF, D_,
            b2 + (long)l * D_, px, D_);
    }
}

// round 14
// speedup vs baseline: 7.4313x; 1.1183x over previous
#include <cuda_runtime.h>
#include <cuda_fp16.h>
#include <math.h>
#include <stdint.h>

#define D_   768
#define H_   12
#define L_   6
#define B_   4
#define N_   1024
#define DH_  64
#define ROWS (B_*N_)      /* 4096 */
#define D3   (3*D_)       /* 2304 */
#define DFF  (4*D_)       /* 3072 */
#define ZHB  (B_*H_)      /* 48   */

#define OFF_QKVT 0
#define OFF_OWT  (768*2304)
#define OFF_W1T  (OFF_OWT + 768*768)
#define OFF_W2T  (OFF_W1T + 768*3072)
#define WT_LSTR  (OFF_W2T + 3072*768)

// ---------------- scratch ----------------------------------------------------
__device__ float  g_x   [ROWS*(size_t)D_];
__device__ __half g_xnh [ROWS*(size_t)D_];
__device__ __half g_qkvh[ROWS*(size_t)D3];
__device__ __half g_atth[ROWS*(size_t)D_];
__device__ __half g_hh  [ROWS*(size_t)DFF];
__device__ __half g_whT [(size_t)L_*WT_LSTR];

__device__ __forceinline__ unsigned pack2(float x, float y) {
    __half2 h = __floats2half2_rn(x, y);
    return *reinterpret_cast<unsigned*>(&h);
}
__device__ __forceinline__ void mma_f16(float* c,
                                        unsigned a0, unsigned a1, unsigned a2, unsigned a3,
                                        unsigned b0, unsigned b1) {
    asm volatile(
        "mma.sync.aligned.m16n8k16.row.col.f32.f16.f16.f32 "
        "{%0,%1,%2,%3}, {%4,%5,%6,%7}, {%8,%9}, {%0,%1,%2,%3};"
        : "+f"(c[0]), "+f"(c[1]), "+f"(c[2]), "+f"(c[3])
        : "r"(a0), "r"(a1), "r"(a2), "r"(a3), "r"(b0), "r"(b1));
}
__device__ __forceinline__ uint32_t smem_u32(const void* p) {
    uint32_t a;
    asm("{ .reg .u64 t; cvta.to.shared.u64 t, %1; cvt.u32.u64 %0, t; }" : "=r"(a) : "l"(p));
    return a;
}
__device__ __forceinline__ void ldm_x4(unsigned& r0, unsigned& r1, unsigned& r2, unsigned& r3,
                                       uint32_t a) {
    asm volatile("ldmatrix.sync.aligned.m8n8.x4.shared.b16 {%0,%1,%2,%3}, [%4];"
        : "=r"(r0), "=r"(r1), "=r"(r2), "=r"(r3) : "r"(a));
}
__device__ __forceinline__ void ldm_x4t(unsigned& r0, unsigned& r1, unsigned& r2, unsigned& r3,
                                        uint32_t a) {
    asm volatile("ldmatrix.sync.aligned.m8n8.x4.trans.shared.b16 {%0,%1,%2,%3}, [%4];"
        : "=r"(r0), "=r"(r1), "=r"(r2), "=r"(r3) : "r"(a));
}
#define CP16(dst, src) \
    asm volatile("cp.async.cg.shared.global [%0],[%1],16;" :: "r"(dst), "l"(src) : "memory")

// ---------------- batched weight transpose+cvt (z = layer) --------------------
__global__ void tr_hL(const float* __restrict__ src, __half* __restrict__ dst,
                      int R, int C, long srcStr, long dstStr) {
    __shared__ float t[32][33];
    const float* s = src + (long)blockIdx.z * srcStr;
    __half*      d = dst + (long)blockIdx.z * dstStr;
    const int c0 = blockIdx.x * 32, r0 = blockIdx.y * 32;
    const int x = threadIdx.x, y = threadIdx.y;
#pragma unroll
    for (int i = 0; i < 32; i += 8)
        t[y + i][x] = s[(long)(r0 + y + i) * C + c0 + x];
    __syncthreads();
#pragma unroll
    for (int i = 0; i < 32; i += 8)
        d[(long)(c0 + y + i) * R + r0 + x] = __float2half(t[x][y + i]);
}

// ---------------- LayerNorm: 192 threads, float4 ------------------------------
__global__ void ln_kernel(const float* __restrict__ x,
                          const float* __restrict__ g,
                          const float* __restrict__ b,
                          __half* __restrict__ y) {
    const int row = blockIdx.x;
    const float4* xr = (const float4*)(x + (size_t)row * D_);
    const int tid = threadIdx.x;

    float4 v = xr[tid];
    float s  = v.x + v.y + v.z + v.w;
    float s2 = v.x * v.x + v.y * v.y + v.z * v.z + v.w * v.w;
#pragma unroll
    for (int o = 16; o; o >>= 1) {
        s  += __shfl_xor_sync(0xffffffffu, s,  o);
        s2 += __shfl_xor_sync(0xffffffffu, s2, o);
    }
    __shared__ float shs[6], shs2[6];
    const int w = tid >> 5;
    if ((tid & 31) == 0) { shs[w] = s; shs2[w] = s2; }
    __syncthreads();
    s = 0.f; s2 = 0.f;
#pragma unroll
    for (int i = 0; i < 6; ++i) { s += shs[i]; s2 += shs2[i]; }
    const float mean = s * (1.f / D_);
    const float var  = s2 * (1.f / D_) - mean * mean;
    const float rstd = rsqrtf(var + 1e-5f);

    const float4 gg = ((const float4*)g)[tid];
    const float4 bb = ((const float4*)b)[tid];
    float r0 = (v.x - mean) * rstd * gg.x + bb.x;
    float r1 = (v.y - mean) * rstd * gg.y + bb.y;
    float r2 = (v.z - mean) * rstd * gg.z + bb.z;
    float r3 = (v.w - mean) * rstd * gg.w + bb.w;
    uint2 o2 = make_uint2(pack2(r0, r1), pack2(r2, r3));
    *(uint2*)&y[(size_t)row * D_ + tid * 4] = o2;
}

// ---------------- fused flash attention: cp.async double-buffered KV ----------
// smem (halfs): Q[128*72] | stage0: K[128*72] V[128*72] | stage1: K V
#define FL_KOFF (128*72)
#define FL_VOFF (128*72)
#define FL_SSTR (2*128*72)
#define FL_SMEM ((128*72 + 2*FL_SSTR)*2)   /* 92160 bytes */
__global__ void __launch_bounds__(256, 2)
flash_k(const __half* __restrict__ qkv, const float* __restrict__ sw,
        __half* __restrict__ outp) {
    extern __shared__ __half sm[];
    __half (*Qs)[72] = (__half(*)[72]) sm;

    const int tid = threadIdx.x, lane = tid & 31;
    const int gid = lane >> 2, tg = lane & 3;
    const int warp = tid >> 5;
    const int m0 = warp * 16;
    const int bm = blockIdx.x * 128;
    const int z = blockIdx.y, b = z / H_, h = z - b * H_;

    const int roff = (lane & 7) + ((lane >> 3) & 1) * 8;
    const int coff = ((lane >> 4) & 1) * 8;

    const __half* Qg = qkv + ((long)(b * N_ + bm)) * D3 + h * DH_;
    const __half* Kg = qkv + (long)b * N_ * D3 + D_ + h * DH_;
    const __half* Vg = Kg + D_;
    const float* swb = sw + (long)b * N_ * N_;

    // Q tile (pre-scaled by 1/8 in QKV epilogue)
#pragma unroll
    for (int i = 0; i < 4; ++i) {
        int flat = tid + i * 256;
        int r = flat >> 3, j = (flat & 7) * 8;
        *(uint4*)&Qs[r][j] = *(const uint4*)&Qg[(long)r * D3 + j];
    }

    const uint32_t smb = smem_u32(sm);
    const uint32_t qb = smb + (uint32_t)(((m0 + roff) * 72 + coff) * 2);

    // cp.async loader: thread -> (row, 8-half chunk)
    const int lr = tid >> 1;                 // 0..127
    const int ljj = (tid & 1) * 8;           // 0 or 8 -> 2 chunks of 8 halfs? (64 halfs/row = 8 chunks)
    // 128 rows x 8 chunks = 1024 slots; 256 threads -> 4 per thread (handled in loop)

    auto load_kv = [&](int t, int s) {
        const uint32_t base = smb + (uint32_t)((FL_KOFF + s * FL_SSTR) * 2);
        const long g0 = (long)(t * 128);
#pragma unroll
        for (int i = 0; i < 4; ++i) {
            int flat = tid + i * 256;
            int r = flat >> 3, j = (flat & 7) * 8;
            CP16(base + (uint32_t)((r * 72 + j) * 2), Kg + (g0 + r) * D3 + j);
        }
#pragma unroll
        for (int i = 0; i < 4; ++i) {
            int flat = tid + i * 256;
            int r = flat >> 3, j = (flat & 7) * 8;
            CP16(base + (uint32_t)((FL_VOFF + r * 72 + j) * 2), Vg + (g0 + r) * D3 + j);
        }
        asm volatile("cp.async.commit_group;" ::: "memory");
    };

    float m0r = -3.4e38f, m1r = -3.4e38f, l0 = 0.f, l1 = 0.f;
    float oacc[8][4];
#pragma unroll
    for (int jo = 0; jo < 8; ++jo)
#pragma unroll
        for (int q = 0; q < 4; ++q) oacc[jo][q] = 0.f;

    const int T = N_ / 128;
    load_kv(0, 0);
    for (int t = 0; t < T; ++t) {
        const int s = t & 1;
        if (t + 1 < T) {
            load_kv(t + 1, s ^ 1);
            asm volatile("cp.async.wait_group 1;" ::: "memory");
        } else {
            asm volatile("cp.async.wait_group 0;" ::: "memory");
        }
        __syncthreads();

        const uint32_t kbb = smb + (uint32_t)((FL_KOFF + s * FL_SSTR + roff * 72 + coff) * 2);
        const uint32_t vbb = kbb + (uint32_t)(FL_VOFF * 2);
        const int kv0 = t * 128;

        // ---- S = Q K^T ----
        float acc[16][4];
#pragma unroll
        for (int j = 0; j < 16; ++j)
#pragma unroll
            for (int q = 0; q < 4; ++q) acc[j][q] = 0.f;
#pragma unroll
        for (int kt = 0; kt < 4; ++kt) {
            unsigned a0, a1, a2, a3;
            ldm_x4(a0, a1, a2, a3, qb + kt * 32);
#pragma unroll
            for (int j = 0; j < 16; j += 2) {
                unsigned r0, r1, r2, r3;
                ldm_x4(r0, r1, r2, r3, kbb + (uint32_t)((j * 8 * 72 + kt * 16) * 2));
                mma_f16(acc[j],     a0, a1, a2, a3, r0, r2);
                mma_f16(acc[j + 1], a0, a1, a2, a3, r1, r3);
            }
        }

        // ---- + spatial bias; row max ----
        const float* sw0 = swb + (long)(bm + m0 + gid) * N_ + kv0;
        const float* sw1 = sw0 + 8 * N_;
        float mx0 = -3.4e38f, mx1 = -3.4e38f;
#pragma unroll
        for (int j = 0; j < 16; ++j) {
            float2 s0 = *(const float2*)&sw0[j * 8 + tg * 2];
            float2 s1 = *(const float2*)&sw1[j * 8 + tg * 2];
            acc[j][0] += s0.x; acc[j][1] += s0.y;
            acc[j][2] += s1.x; acc[j][3] += s1.y;
            mx0 = fmaxf(mx0, fmaxf(acc[j][0], acc[j][1]));
            mx1 = fmaxf(mx1, fmaxf(acc[j][2], acc[j][3]));
        }
#pragma unroll
        for (int o = 1; o <= 2; o <<= 1) {
            mx0 = fmaxf(mx0, __shfl_xor_sync(0xffffffffu, mx0, o));
            mx1 = fmaxf(mx1, __shfl_xor_sync(0xffffffffu, mx1, o));
        }

        const float mn0 = fmaxf(m0r, mx0), mn1 = fmaxf(m1r, mx1);
        const float sc0 = __expf(m0r - mn0), sc1 = __expf(m1r - mn1);
        m0r = mn0; m1r = mn1;

        float rs0 = 0.f, rs1 = 0.f;
        unsigned pr[16][2];
#pragma unroll
        for (int j = 0; j < 16; ++j) {
            float p0 = __expf(acc[j][0] - mn0);
            float p1 = __expf(acc[j][1] - mn0);
            float p2 = __expf(acc[j][2] - mn1);
            float p3 = __expf(acc[j][3] - mn1);
            rs0 += p0 + p1; rs1 += p2 + p3;
            pr[j][0] = pack2(p0, p1);
            pr[j][1] = pack2(p2, p3);
        }
#pragma unroll
        for (int o = 1; o <= 2; o <<= 1) {
            rs0 += __shfl_xor_sync(0xffffffffu, rs0, o);
            rs1 += __shfl_xor_sync(0xffffffffu, rs1, o);
        }
        l0 = l0 * sc0 + rs0;
        l1 = l1 * sc1 + rs1;

#pragma unroll
        for (int jo = 0; jo < 8; ++jo) {
            oacc[jo][0] *= sc0; oacc[jo][1] *= sc0;
            oacc[jo][2] *= sc1; oacc[jo][3] *= sc1;
        }
#pragma unroll
        for (int kt2 = 0; kt2 < 8; ++kt2) {
            unsigned a0 = pr[2 * kt2][0],     a1 = pr[2 * kt2][1];
            unsigned a2 = pr[2 * kt2 + 1][0], a3 = pr[2 * kt2 + 1][1];
#pragma unroll
            for (int jo = 0; jo < 8; jo += 2) {
                unsigned r0, r1, r2, r3;
                ldm_x4t(r0, r1, r2, r3, vbb + (uint32_t)(((kt2 * 16) * 72 + jo * 8) * 2));
                mma_f16(oacc[jo],     a0, a1, a2, a3, r0, r1);
                mma_f16(oacc[jo + 1], a0, a1, a2, a3, r2, r3);
            }
        }
        __syncthreads();   // all reads of buffer s done before next load overwrites
    }

    const float i0 = 1.f / l0, i1 = 1.f / l1;
    __half* o0 = outp + (long)(b * N_ + bm + m0 + gid) * D_ + h * DH_;
    __half* o1 = o0 + 8 * D_;
#pragma unroll
    for (int jo = 0; jo < 8; ++jo) {
        *(unsigned*)&o0[jo * 8 + tg * 2] = pack2(oacc[jo][0] * i0, oacc[jo][1] * i0);
        *(unsigned*)&o1[jo * 8 + tg * 2] = pack2(oacc[jo][2] * i1, oacc[jo][3] * i1);
    }
}

// ---------------- fp16 GEMM: 64x128xBK64, 2-stage, 3 CTAs/SM (unchanged) ------
#define G5_SK    72
#define G5_BM    64
#define G5_BN    128
#define G5_ATILE (G5_BM*G5_SK)
#define G5_STAGE ((G5_BM+G5_BN)*G5_SK)
#define G5_SMEM  (2*G5_STAGE*2)
template<int FLAGS>
__global__ void __launch_bounds__(256, 3)
gemm_h5(const __half* __restrict__ A, const __half* __restrict__ B,
        void* __restrict__ Cv, int K, int lda, int ldc,
        const float* __restrict__ bias,
        const float* __restrict__ resid, int ldres) {
    extern __shared__ __half sm5[];
    const int tid  = threadIdx.x;
    const int lane = tid & 31;
    const int gid  = lane >> 2;
    const int tg   = lane & 3;
    const int warp = tid >> 5;
    const int mwarp = (warp >> 2) * 32;
    const int nwarp = (warp & 3) * 32;
    const int bn = blockIdx.x * G5_BN;
    const int bm = blockIdx.y * G5_BM;

    const uint32_t smb = smem_u32(sm5);
    const int roff = (lane & 7) + ((lane >> 3) & 1) * 8;
    const int coff = ((lane >> 4) & 1) * 8;
    const uint32_t aAb = smb + (uint32_t)(((mwarp + roff) * G5_SK + coff) * 2);
    const uint32_t aBb = smb + (uint32_t)((G5_ATILE + (nwarp + roff) * G5_SK + coff) * 2);

    float acc[2][4][4] = {};
    const int T = K >> 6;

    auto load = [&](int t, int s) {
        const uint32_t base = smb + (uint32_t)(s * G5_STAGE * 2);
        const long ko = (long)t * 64;
#pragma unroll
        for (int i = 0; i < 2; ++i) {
            int flat = tid + i * 256;
            int r = flat >> 3, c = (flat & 7) * 8;
            CP16(base + (uint32_t)((r * G5_SK + c) * 2),
                 A + (long)(bm + r) * lda + ko + c);
        }
#pragma unroll
        for (int i = 0; i < 4; ++i) {
            int flat = tid + i * 256;
            int r = flat >> 3, c = (flat & 7) * 8;
            CP16(base + (uint32_t)((G5_ATILE + r * G5_SK + c) * 2),
                 B + (long)(bn + r) * K + ko + c);
        }
        asm volatile("cp.async.commit_group;" ::: "memory");
    };

    load(0, 0);
    for (int t = 0; t < T; ++t) {
        const int s = t & 1;
        if (t + 1 < T) {
            load(t + 1, s ^ 1);
            asm volatile("cp.async.wait_group 1;" ::: "memory");
        } else {
            asm volatile("cp.async.wait_group 0;" ::: "memory");
        }
        __syncthreads();

        const uint32_t sb_ = (uint32_t)(s * G5_STAGE * 2);
#pragma unroll
        for (int ks = 0; ks < 4; ++ks) {
            unsigned af[2][4];
#pragma unroll
            for (int i = 0; i < 2; ++i)
                ldm_x4(af[i][0], af[i][1], af[i][2], af[i][3],
                       aAb + sb_ + (uint32_t)((i * 16 * G5_SK + ks * 16) * 2));
            unsigned bf[4][2];
#pragma unroll
            for (int jp = 0; jp < 4; jp += 2)
                ldm_x4(bf[jp][0], bf[jp + 1][0], bf[jp][1], bf[jp + 1][1],
                       aBb + sb_ + (uint32_t)((jp * 8 * G5_SK + ks * 16) * 2));
#pragma unroll
            for (int i = 0; i < 2; ++i)
#pragma unroll
                for (int j = 0; j < 4; ++j)
                    mma_f16(acc[i][j], af[i][0], af[i][1], af[i][2], af[i][3],
                            bf[j][0], bf[j][1]);
        }
        __syncthreads();
    }

#pragma unroll
    for (int i = 0; i < 2; ++i) {
        const int r0 = bm + mwarp + i * 16 + gid;
#pragma unroll
        for (int j = 0; j < 4; ++j) {
            const int c = bn + nwarp + j * 8 + tg * 2;
#pragma unroll
            for (int hh = 0; hh < 2; ++hh) {
                const int row = r0 + hh * 8;
                float2 p = make_float2(acc[i][j][hh * 2], acc[i][j][hh * 2 + 1]);
                if (FLAGS & 16) { const float sc = (c < D_) ? 0.125f : 1.f; p.x *= sc; p.y *= sc; }
                if (FLAGS & 1)  { p.x += bias[c]; p.y += bias[c + 1]; }
                if (FLAGS & 2)  {
                    p.x = 0.5f * p.x * (1.f + erff(p.x * 0.70710678118654752f));
                    p.y = 0.5f * p.y * (1.f + erff(p.y * 0.70710678118654752f));
                }
                if (FLAGS & 4)  {
                    float2 r = *(const float2*)&resid[(long)row * ldres + c];
                    p.x += r.x; p.y += r.y;
                }
                if (FLAGS & 8)
                    *(unsigned*)&((__half*)Cv)[(long)row * ldc + c] = pack2(p.x, p.y);
                else
                    *(float2*)&((float*)Cv)[(long)row * ldc + c] = p;
            }
        }
    }
}

// ---------------- launch ------------------------------------------------------
extern "C" void kernel_launch(void* const* d_in, const int* in_sizes, int n_in,
                              void* d_out, int out_size) {
    const float* x_in  = (const float*)d_in[0];
    const float* sw    = (const float*)d_in[1];
    const float* ln1g  = (const float*)d_in[2];
    const float* ln1b  = (const float*)d_in[3];
    const float* wqkv  = (const float*)d_in[4];
    const float* wout  = (const float*)d_in[5];
    const float* bout  = (const float*)d_in[6];
    const float* ln2g  = (const float*)d_in[7];
    const float* ln2b  = (const float*)d_in[8];
    const float* w1    = (const float*)d_in[9];
    const float* b1    = (const float*)d_in[10];
    const float* w2    = (const float*)d_in[11];
    const float* b2    = (const float*)d_in[12];
    float* out = (float*)d_out;

    float *px;
    __half *pxn, *pqkv, *patt, *ph, *pwT;
    cudaGetSymbolAddress((void**)&px,   g_x);
    cudaGetSymbolAddress((void**)&pxn,  g_xnh);
    cudaGetSymbolAddress((void**)&pqkv, g_qkvh);
    cudaGetSymbolAddress((void**)&patt, g_atth);
    cudaGetSymbolAddress((void**)&ph,   g_hh);
    cudaGetSymbolAddress((void**)&pwT,  g_whT);

    cudaFuncSetAttribute(flash_k, cudaFuncAttributeMaxDynamicSharedMemorySize, FL_SMEM);
    cudaFuncSetAttribute(gemm_h5<8|16>,  cudaFuncAttributeMaxDynamicSharedMemorySize, G5_SMEM);
    cudaFuncSetAttribute(gemm_h5<1|4>,   cudaFuncAttributeMaxDynamicSharedMemorySize, G5_SMEM);
    cudaFuncSetAttribute(gemm_h5<1|2|8>, cudaFuncAttributeMaxDynamicSharedMemorySize, G5_SMEM);

    tr_hL<<<dim3(D3/32, D_/32, L_),  dim3(32,8)>>>(wqkv, pwT + OFF_QKVT, D_, D3,
                                                   (long)D_*D3,  (long)WT_LSTR);
    tr_hL<<<dim3(D_/32, D_/32, L_),  dim3(32,8)>>>(wout, pwT + OFF_OWT,  D_, D_,
                                                   (long)D_*D_,  (long)WT_LSTR);
    tr_hL<<<dim3(DFF/32, D_/32, L_), dim3(32,8)>>>(w1,   pwT + OFF_W1T,  D_, DFF,
                                                   (long)D_*DFF, (long)WT_LSTR);
    tr_hL<<<dim3(D_/32, DFF/32, L_), dim3(32,8)>>>(w2,   pwT + OFF_W2T,  DFF, D_,
                                                   (long)DFF*D_, (long)WT_LSTR);

    for (int l = 0; l < L_; ++l) {
        const float* xcur = (l == 0) ? x_in : px;
        __half* wl = pwT + (size_t)l * WT_LSTR;

        ln_kernel<<<ROWS, 192>>>(xcur, ln1g + (long)l * D_, ln1b + (long)l * D_, pxn);

        gemm_h5<8|16><<<dim3(D3/128, ROWS/64), 256, G5_SMEM>>>(
            pxn, wl + OFF_QKVT, pqkv, D_, D_, D3, nullptr, nullptr, 0);

        flash_k<<<dim3(N_/128, ZHB), 256, FL_SMEM>>>(pqkv, sw, patt);

        gemm_h5<1|4><<<dim3(D_/128, ROWS/64), 256, G5_SMEM>>>(
            patt, wl + OFF_OWT, px, D_, D_, D_,
            bout + (long)l * D_, xcur, D_);

        ln_kernel<<<ROWS, 192>>>(px, ln2g + (long)l * D_, ln2b + (long)l * D_, pxn);

        gemm_h5<1|2|8><<<dim3(DFF/128, ROWS/64), 256, G5_SMEM>>>(
            pxn, wl + OFF_W1T, ph, D_, D_, DFF,
            b1 + (long)l * DFF, nullptr, 0);

        float* cdst = (l == L_ - 1) ? out : px;
        gemm_h5<1|4><<<dim3(D_/128, ROWS/64), 256, G5_SMEM>>>(
            ph, wl + OFF_W2T, cdst, DFF, DFF, D_,
            b2 + (long)l * D_, px, D_);
    }
}